// round 12
// baseline (speedup 1.0000x reference)
#include <cuda_runtime.h>
#include <cstdint>

#define Bc   256
#define Nc   1024
#define Dc   128
#define QSc  256
#define HIDc 256
#define NTHR 512
#define RES_ROWS 576   // rows [0,576): 128 CTA * 2 * 576 * 512B = 72 MB pinned
#define RSTR 20        // red row stride (floats), STS.128-aligned

// Folded weights (q_star[:128] == h lets W_ih[:, :128] + W_hh fold):
__device__ float4 g_Wq4[Dc * Dc];
__device__ float4 g_Wr4[Dc * Dc];
__device__ float4 g_bias4[Dc];
__device__ float  g_WlinT[QSc * HIDc];

// ---- dynamic SMEM (bytes) — no x staging anymore ----
#define OFF_GP   0                            // float4[2][4][128]
#define SZ_GP    16384
#define OFF_RED  (OFF_GP + SZ_GP)             // float[2][256][RSTR]
#define SZ_RED   (2 * 256 * RSTR * 4)
#define OFF_PART (OFF_RED + SZ_RED)           // float[512]
#define SZ_PART  (512 * 4)
#define OFF_LRED (OFF_PART + SZ_PART)         // float[2][8]
#define SZ_LRED  64
#define OFF_SQ   (OFF_LRED + SZ_LRED)         // float[2][256] = [q|r]
#define SZ_SQ    (2 * 256 * 4)
#define SMEM_TOTAL (OFF_SQ + SZ_SQ)           // ~61.5 KB

__global__ void prep_kernel(const float* __restrict__ W_ih,
                            const float* __restrict__ W_hh,
                            const float* __restrict__ b_ih,
                            const float* __restrict__ b_hh,
                            const float* __restrict__ W_lin) {
    int tid = blockIdx.x * blockDim.x + threadIdx.x;
    int nt  = gridDim.x * blockDim.x;
    for (int idx = tid; idx < Dc * Dc; idx += nt) {
        int c = idx >> 7, d = idx & 127;
        float4 w;
        w.x = W_ih[(d      ) * QSc + c] + W_hh[(d      ) * Dc + c];
        w.y = W_ih[(d + 128) * QSc + c] + W_hh[(d + 128) * Dc + c];
        w.z = W_ih[(d + 256) * QSc + c] + W_hh[(d + 256) * Dc + c];
        w.w = W_ih[(d + 384) * QSc + c] + W_hh[(d + 384) * Dc + c];
        g_Wq4[idx] = w;
        float4 v;
        v.x = W_ih[(d      ) * QSc + 128 + c];
        v.y = W_ih[(d + 128) * QSc + 128 + c];
        v.z = W_ih[(d + 256) * QSc + 128 + c];
        v.w = W_ih[(d + 384) * QSc + 128 + c];
        g_Wr4[idx] = v;
    }
    for (int d = tid; d < Dc; d += nt) {
        float4 bb;
        bb.x = b_ih[d      ] + b_hh[d      ];
        bb.y = b_ih[d + 128] + b_hh[d + 128];
        bb.z = b_ih[d + 256] + b_hh[d + 256];
        bb.w = b_ih[d + 384] + b_hh[d + 384];
        g_bias4[d] = bb;
    }
    for (int idx = tid; idx < QSc * HIDc; idx += nt) {
        int c = idx >> 8, o = idx & 255;
        g_WlinT[idx] = W_lin[o * QSc + c];
    }
}

__device__ __forceinline__ float sigf(float x) {
    return __fdividef(1.0f, 1.0f + __expf(-x));
}
__device__ __forceinline__ float tanh_acc(float x) {
    return __fdividef(2.0f, 1.0f + __expf(-2.0f * x)) - 1.0f;
}
// read-only global LDG.128 with an L2 eviction-policy hint
__device__ __forceinline__ float4 ldg_pol(const float4* p, uint64_t pol) {
    float4 v;
    asm("ld.global.nc.L2::cache_hint.v4.f32 {%0,%1,%2,%3}, [%4], %5;"
        : "=f"(v.x), "=f"(v.y), "=f"(v.z), "=f"(v.w)
        : "l"(p), "l"(pol));
    return v;
}

// 128 CTAs x 512 threads, 2 batches/CTA.
// Warps 0-7: attention — DIRECT L2 streaming (x is L2-pinned; no SMEM staging,
// no cp.async, no per-tile barriers). Warps 8-15: next step's q-part GEMV.
__global__ void __launch_bounds__(NTHR, 1)
s2s_kernel(const float* __restrict__ x,
           const float* __restrict__ b_lin,
           float* __restrict__ out) {
    extern __shared__ char smem[];
    float4* gp   = (float4*)(smem + OFF_GP);
    float*  red  = (float*)(smem + OFF_RED);
    float*  part = (float*)(smem + OFF_PART);
    float*  lred = (float*)(smem + OFF_LRED);
    float*  sq   = (float*)(smem + OFF_SQ);   // per batch: [q(128) | r(128)]

    const int tid  = threadIdx.x;
    const int d    = tid & 127;
    const int p    = tid >> 7;
    const int lane = tid & 31;
    const int wrp  = tid >> 5;                // attn warps: 0..7
    const bool is_attn = (tid < 256);

    uint64_t pol_last, pol_first;
    asm("createpolicy.fractional.L2::evict_last.b64 %0, 1.0;"  : "=l"(pol_last));
    asm("createpolicy.fractional.L2::evict_first.b64 %0, 1.0;" : "=l"(pol_first));

    if (tid < 512) sq[tid] = 0.0f;
    float c_state = 0.0f;

    const float4* xa  = (const float4*)(x + (size_t)(blockIdx.x * 2    ) * Nc * Dc);
    const float4* xbp = (const float4*)(x + (size_t)(blockIdx.x * 2 + 1) * Nc * Dc);

    // attention thread -> (row group q0, 16-dim chunk j)
    const int q0 = (tid & 255) >> 3;          // 0..31 ; rows q0 + 32*it
    const int j  = tid & 7;

    const int p2 = (tid >> 7) - 2;
    const float4* Wqp = g_Wq4 + (size_t)(64 * (p2 & 1)) * Dc + d;
    const float4* Wrp = g_Wr4 + (size_t)(32 * p) * Dc + d;
    const float4  bias = g_bias4[d];
    float4 qacc_a = make_float4(0.f,0.f,0.f,0.f);
    float4 qacc_b = make_float4(0.f,0.f,0.f,0.f);

    __syncthreads();

    for (int t = 0; t < Nc; t++) {
        // ---- serial r-GEMV: 32 r-cols/thread; gate warps fold carried qacc ----
        {
            float4 aa, ab;
            if (is_attn) {
                aa = make_float4(0.f,0.f,0.f,0.f);
                ab = make_float4(0.f,0.f,0.f,0.f);
            } else {
                aa = qacc_a; ab = qacc_b;
                qacc_a = make_float4(0.f,0.f,0.f,0.f);
                qacc_b = make_float4(0.f,0.f,0.f,0.f);
            }
            const float* ra = sq +       128 + 32 * p;
            const float* rb = sq + 256 + 128 + 32 * p;
            #pragma unroll 8
            for (int cr = 0; cr < 32; cr++) {
                float va = ra[cr], vb = rb[cr];
                float4 w = Wrp[cr * Dc];
                aa.x=fmaf(va,w.x,aa.x); aa.y=fmaf(va,w.y,aa.y); aa.z=fmaf(va,w.z,aa.z); aa.w=fmaf(va,w.w,aa.w);
                ab.x=fmaf(vb,w.x,ab.x); ab.y=fmaf(vb,w.y,ab.y); ab.z=fmaf(vb,w.z,ab.z); ab.w=fmaf(vb,w.w,ab.w);
            }
            gp[(0 * 4 + p) * Dc + d] = aa;
            gp[(1 * 4 + p) * Dc + d] = ab;
        }
        __syncthreads();

        // ---- LSTM cell (threads 0..255) ----
        if (tid < 256) {
            int bt = tid >> 7;
            float4 s0 = gp[(bt*4+0)*Dc + d];
            float4 s1 = gp[(bt*4+1)*Dc + d];
            float4 s2 = gp[(bt*4+2)*Dc + d];
            float4 s3 = gp[(bt*4+3)*Dc + d];
            float gi = s0.x+s1.x+s2.x+s3.x + bias.x;
            float gf = s0.y+s1.y+s2.y+s3.y + bias.y;
            float gg = s0.z+s1.z+s2.z+s3.z + bias.z;
            float go = s0.w+s1.w+s2.w+s3.w + bias.w;
            c_state = fmaf(sigf(gf), c_state, sigf(gi) * tanh_acc(gg));
            float h = sigf(go) * tanh_acc(c_state);
            sq[bt*256 + d] = h;   // q(t+1)
        }
        __syncthreads();

        if (is_attn) {
            // ======== attention: direct-L2 stream, 32 row-iters, no barriers ====
            float4 qr[2][4];
            #pragma unroll
            for (int bt = 0; bt < 2; bt++)
                #pragma unroll
                for (int i = 0; i < 4; i++)
                    qr[bt][i] = *(const float4*)(sq + bt*256 + 16*j + 4*i);

            float rp[2][16];
            float lac[2] = {0.0f, 0.0f};
            #pragma unroll
            for (int bt = 0; bt < 2; bt++)
                #pragma unroll
                for (int k = 0; k < 16; k++) rp[bt][k] = 0.0f;

            const float4* pa0 = xa  + (size_t)q0 * 32 + 4 * j;
            const float4* pb0 = xbp + (size_t)q0 * 32 + 4 * j;

            #pragma unroll 2
            for (int it = 0; it < 32; it++) {
                int n = q0 + (it << 5);
                uint64_t pol = (n < RES_ROWS) ? pol_last : pol_first;
                const float4* pa = pa0 + (size_t)it * 1024;   // 32 rows * 32 f4
                const float4* pb = pb0 + (size_t)it * 1024;

                float4 xra[4], xrb[4];
                #pragma unroll
                for (int i = 0; i < 4; i++) xra[i] = ldg_pol(pa + i, pol);
                #pragma unroll
                for (int i = 0; i < 4; i++) xrb[i] = ldg_pol(pb + i, pol);

                // batch a  (same accumulation order as R11 -> bit-identical)
                {
                    float e = 0.0f;
                    #pragma unroll
                    for (int i = 0; i < 4; i++) {
                        e = fmaf(xra[i].x, qr[0][i].x, e);
                        e = fmaf(xra[i].y, qr[0][i].y, e);
                        e = fmaf(xra[i].z, qr[0][i].z, e);
                        e = fmaf(xra[i].w, qr[0][i].w, e);
                    }
                    e += __shfl_xor_sync(0xffffffffu, e, 1);
                    e += __shfl_xor_sync(0xffffffffu, e, 2);
                    e += __shfl_xor_sync(0xffffffffu, e, 4);
                    float pw = __expf(e - 40.0f);   // |e| << 40 by construction
                    lac[0] += pw;
                    #pragma unroll
                    for (int i = 0; i < 4; i++) {
                        rp[0][4*i+0] = fmaf(pw, xra[i].x, rp[0][4*i+0]);
                        rp[0][4*i+1] = fmaf(pw, xra[i].y, rp[0][4*i+1]);
                        rp[0][4*i+2] = fmaf(pw, xra[i].z, rp[0][4*i+2]);
                        rp[0][4*i+3] = fmaf(pw, xra[i].w, rp[0][4*i+3]);
                    }
                }
                // batch b
                {
                    float e = 0.0f;
                    #pragma unroll
                    for (int i = 0; i < 4; i++) {
                        e = fmaf(xrb[i].x, qr[1][i].x, e);
                        e = fmaf(xrb[i].y, qr[1][i].y, e);
                        e = fmaf(xrb[i].z, qr[1][i].z, e);
                        e = fmaf(xrb[i].w, qr[1][i].w, e);
                    }
                    e += __shfl_xor_sync(0xffffffffu, e, 1);
                    e += __shfl_xor_sync(0xffffffffu, e, 2);
                    e += __shfl_xor_sync(0xffffffffu, e, 4);
                    float pw = __expf(e - 40.0f);
                    lac[1] += pw;
                    #pragma unroll
                    for (int i = 0; i < 4; i++) {
                        rp[1][4*i+0] = fmaf(pw, xrb[i].x, rp[1][4*i+0]);
                        rp[1][4*i+1] = fmaf(pw, xrb[i].y, rp[1][4*i+1]);
                        rp[1][4*i+2] = fmaf(pw, xrb[i].z, rp[1][4*i+2]);
                        rp[1][4*i+3] = fmaf(pw, xrb[i].w, rp[1][4*i+3]);
                    }
                }
            }

            // per-warp L reduce (lanes in a j-group hold identical pw)
            #pragma unroll
            for (int bt = 0; bt < 2; bt++) {
                float lv = lac[bt];
                lv += __shfl_xor_sync(0xffffffffu, lv, 8);
                lv += __shfl_xor_sync(0xffffffffu, lv, 16);
                if (lane == 0) lred[bt * 8 + wrp] = lv;
                float* rw = red + (size_t)(bt * 256 + tid) * RSTR;
                #pragma unroll
                for (int i = 0; i < 4; i++)
                    *(float4*)(rw + 4 * i) = make_float4(rp[bt][4*i+0], rp[bt][4*i+1],
                                                         rp[bt][4*i+2], rp[bt][4*i+3]);
            }
        } else {
            // ======== gate warps: folded q-GEMV for NEXT step ========
            const float* qa = sq +       64 * (p2 & 1);
            const float* qb = sq + 256 + 64 * (p2 & 1);
            #pragma unroll 8
            for (int c = 0; c < 64; c++) {
                float va = qa[c], vb = qb[c];
                float4 w = Wqp[c * Dc];
                qacc_a.x=fmaf(va,w.x,qacc_a.x); qacc_a.y=fmaf(va,w.y,qacc_a.y);
                qacc_a.z=fmaf(va,w.z,qacc_a.z); qacc_a.w=fmaf(va,w.w,qacc_a.w);
                qacc_b.x=fmaf(vb,w.x,qacc_b.x); qacc_b.y=fmaf(vb,w.y,qacc_b.y);
                qacc_b.z=fmaf(vb,w.z,qacc_b.z); qacc_b.w=fmaf(vb,w.w,qacc_b.w);
            }
        }
        __syncthreads();

        // ---- phase 1: rsum halves across ALL 512 threads (16 iters each) ----
        {
            int pair = tid & 255, half = tid >> 8;
            int bt = pair >> 7, dd = pair & 127;
            int jj = dd >> 4, kk = dd & 15;
            const float* base = red + (size_t)(bt * 256 + half * 128 + jj) * RSTR + kk;
            float sacc = 0.0f;
            #pragma unroll
            for (int qq = 0; qq < 16; qq++)
                sacc += base[qq * 8 * RSTR];
            part[tid] = sacc;
        }
        __syncthreads();

        // ---- phase 2: combine + normalize (threads 0..255) ----
        if (tid < 256) {
            int bt = tid >> 7;
            float rsum = part[tid] + part[tid + 256];
            float Lx = ((lred[bt*8+0] + lred[bt*8+1]) + (lred[bt*8+2] + lred[bt*8+3]))
                     + ((lred[bt*8+4] + lred[bt*8+5]) + (lred[bt*8+6] + lred[bt*8+7]));
            sq[bt*256 + 128 + d] = __fdividef(rsum, Lx);
        }
        __syncthreads();
    }

    // ---- epilogue: out = q_star @ W_lin^T + b_lin ----
    {
        int bt = tid >> 8;
        int o  = tid & 255;
        float acc = b_lin[o];
        #pragma unroll 8
        for (int c = 0; c < QSc; c++)
            acc = fmaf(sq[bt*256 + c], g_WlinT[c * HIDc + o], acc);
        out[(size_t)(blockIdx.x * 2 + bt) * HIDc + o] = acc;
    }
}

extern "C" void kernel_launch(void* const* d_in, const int* in_sizes, int n_in,
                              void* d_out, int out_size) {
    const float* x     = (const float*)d_in[0];
    const float* W_ih  = (const float*)d_in[1];
    const float* W_hh  = (const float*)d_in[2];
    const float* b_ih  = (const float*)d_in[3];
    const float* b_hh  = (const float*)d_in[4];
    const float* W_lin = (const float*)d_in[5];
    const float* b_lin = (const float*)d_in[6];
    float* out = (float*)d_out;

    cudaFuncSetAttribute(s2s_kernel, cudaFuncAttributeMaxDynamicSharedMemorySize,
                         SMEM_TOTAL);
    prep_kernel<<<256, 256>>>(W_ih, W_hh, b_ih, b_hh, W_lin);
    s2s_kernel<<<Bc / 2, NTHR, SMEM_TOTAL>>>(x, b_lin, out);
}

// round 13
// speedup vs baseline: 1.1695x; 1.1695x over previous
#include <cuda_runtime.h>
#include <cstdint>

#define Bc   256
#define Nc   1024
#define Dc   128
#define QSc  256
#define HIDc 256
#define NTHR 512
#define RES_IT 18      // iters [0,18): rows < 576 pinned (72 MB chipwide)
#define RSTR 20        // red row stride (floats), STS.128-aligned

// Folded weights (q_star[:128] == h lets W_ih[:, :128] + W_hh fold):
__device__ float4 g_Wq4[Dc * Dc];
__device__ float4 g_Wr4[Dc * Dc];
__device__ float4 g_bias4[Dc];
__device__ float  g_WlinT[QSc * HIDc];

// ---- dynamic SMEM (bytes) — no x staging ----
#define OFF_GP   0                            // float4[2][4][128]
#define SZ_GP    16384
#define OFF_RED  (OFF_GP + SZ_GP)             // float[2][256][RSTR]
#define SZ_RED   (2 * 256 * RSTR * 4)
#define OFF_PART (OFF_RED + SZ_RED)           // float[512]
#define SZ_PART  (512 * 4)
#define OFF_LRED (OFF_PART + SZ_PART)         // float[2][8]
#define SZ_LRED  64
#define OFF_SQ   (OFF_LRED + SZ_LRED)         // float[2][256] = [q|r]
#define SZ_SQ    (2 * 256 * 4)
#define SMEM_TOTAL (OFF_SQ + SZ_SQ)           // ~61.5 KB

__global__ void prep_kernel(const float* __restrict__ W_ih,
                            const float* __restrict__ W_hh,
                            const float* __restrict__ b_ih,
                            const float* __restrict__ b_hh,
                            const float* __restrict__ W_lin) {
    int tid = blockIdx.x * blockDim.x + threadIdx.x;
    int nt  = gridDim.x * blockDim.x;
    for (int idx = tid; idx < Dc * Dc; idx += nt) {
        int c = idx >> 7, d = idx & 127;
        float4 w;
        w.x = W_ih[(d      ) * QSc + c] + W_hh[(d      ) * Dc + c];
        w.y = W_ih[(d + 128) * QSc + c] + W_hh[(d + 128) * Dc + c];
        w.z = W_ih[(d + 256) * QSc + c] + W_hh[(d + 256) * Dc + c];
        w.w = W_ih[(d + 384) * QSc + c] + W_hh[(d + 384) * Dc + c];
        g_Wq4[idx] = w;
        float4 v;
        v.x = W_ih[(d      ) * QSc + 128 + c];
        v.y = W_ih[(d + 128) * QSc + 128 + c];
        v.z = W_ih[(d + 256) * QSc + 128 + c];
        v.w = W_ih[(d + 384) * QSc + 128 + c];
        g_Wr4[idx] = v;
    }
    for (int d = tid; d < Dc; d += nt) {
        float4 bb;
        bb.x = b_ih[d      ] + b_hh[d      ];
        bb.y = b_ih[d + 128] + b_hh[d + 128];
        bb.z = b_ih[d + 256] + b_hh[d + 256];
        bb.w = b_ih[d + 384] + b_hh[d + 384];
        g_bias4[d] = bb;
    }
    for (int idx = tid; idx < QSc * HIDc; idx += nt) {
        int c = idx >> 8, o = idx & 255;
        g_WlinT[idx] = W_lin[o * QSc + c];
    }
}

__device__ __forceinline__ float sigf(float x) {
    return __fdividef(1.0f, 1.0f + __expf(-x));
}
__device__ __forceinline__ float tanh_acc(float x) {
    return __fdividef(2.0f, 1.0f + __expf(-2.0f * x)) - 1.0f;
}
__device__ __forceinline__ float4 ldg_pol(const float4* p, uint64_t pol) {
    float4 v;
    asm("ld.global.nc.L2::cache_hint.v4.f32 {%0,%1,%2,%3}, [%4], %5;"
        : "=f"(v.x), "=f"(v.y), "=f"(v.z), "=f"(v.w)
        : "l"(p), "l"(pol));
    return v;
}

// 128 CTAs x 512 threads, 2 batches/CTA.
// Warps 0-7: attention — direct L2 stream with SECTOR-MINIMAL mapping:
//   lane = rowpart(2b)*8 + j(3b); warp LDG.128 i covers 4 rows x 128B contiguous
//   (16 sectors, the coalescing minimum). Thread's dims: {32i + 4j + k}.
// Warps 8-15: next step's q-part GEMV.
__global__ void __launch_bounds__(NTHR, 1)
s2s_kernel(const float* __restrict__ x,
           const float* __restrict__ b_lin,
           float* __restrict__ out) {
    extern __shared__ char smem[];
    float4* gp   = (float4*)(smem + OFF_GP);
    float*  red  = (float*)(smem + OFF_RED);
    float*  part = (float*)(smem + OFF_PART);
    float*  lred = (float*)(smem + OFF_LRED);
    float*  sq   = (float*)(smem + OFF_SQ);   // per batch: [q(128) | r(128)]

    const int tid  = threadIdx.x;
    const int d    = tid & 127;
    const int p    = tid >> 7;
    const int lane = tid & 31;
    const int wrp  = tid >> 5;                // attn warps: 0..7
    const bool is_attn = (tid < 256);

    uint64_t pol_last, pol_first;
    asm("createpolicy.fractional.L2::evict_last.b64 %0, 1.0;"  : "=l"(pol_last));
    asm("createpolicy.fractional.L2::evict_first.b64 %0, 1.0;" : "=l"(pol_first));

    if (tid < 512) sq[tid] = 0.0f;
    float c_state = 0.0f;

    const float4* xa  = (const float4*)(x + (size_t)(blockIdx.x * 2    ) * Nc * Dc);
    const float4* xbp = (const float4*)(x + (size_t)(blockIdx.x * 2 + 1) * Nc * Dc);

    // attention mapping: row = 32*it + wrp*4 + rp8 ; dims = 32*i + 4*j + k
    const int rp8 = lane >> 3;                // 0..3  (row within warp group)
    const int j   = lane & 7;                 // dim sub-chunk

    const int p2 = (tid >> 7) - 2;
    const float4* Wqp = g_Wq4 + (size_t)(64 * (p2 & 1)) * Dc + d;
    const float4* Wrp = g_Wr4 + (size_t)(32 * p) * Dc + d;
    const float4  bias = g_bias4[d];
    float4 qacc_a = make_float4(0.f,0.f,0.f,0.f);
    float4 qacc_b = make_float4(0.f,0.f,0.f,0.f);

    __syncthreads();

    for (int t = 0; t < Nc; t++) {
        // ---- serial r-GEMV: 32 r-cols/thread; gate warps fold carried qacc ----
        {
            float4 aa, ab;
            if (is_attn) {
                aa = make_float4(0.f,0.f,0.f,0.f);
                ab = make_float4(0.f,0.f,0.f,0.f);
            } else {
                aa = qacc_a; ab = qacc_b;
                qacc_a = make_float4(0.f,0.f,0.f,0.f);
                qacc_b = make_float4(0.f,0.f,0.f,0.f);
            }
            const float* ra = sq +       128 + 32 * p;
            const float* rb = sq + 256 + 128 + 32 * p;
            #pragma unroll 8
            for (int cr = 0; cr < 32; cr++) {
                float va = ra[cr], vb = rb[cr];
                float4 w = Wrp[cr * Dc];
                aa.x=fmaf(va,w.x,aa.x); aa.y=fmaf(va,w.y,aa.y); aa.z=fmaf(va,w.z,aa.z); aa.w=fmaf(va,w.w,aa.w);
                ab.x=fmaf(vb,w.x,ab.x); ab.y=fmaf(vb,w.y,ab.y); ab.z=fmaf(vb,w.z,ab.z); ab.w=fmaf(vb,w.w,ab.w);
            }
            gp[(0 * 4 + p) * Dc + d] = aa;
            gp[(1 * 4 + p) * Dc + d] = ab;
        }
        __syncthreads();

        // ---- LSTM cell (threads 0..255) ----
        if (tid < 256) {
            int bt = tid >> 7;
            float4 s0 = gp[(bt*4+0)*Dc + d];
            float4 s1 = gp[(bt*4+1)*Dc + d];
            float4 s2 = gp[(bt*4+2)*Dc + d];
            float4 s3 = gp[(bt*4+3)*Dc + d];
            float gi = s0.x+s1.x+s2.x+s3.x + bias.x;
            float gf = s0.y+s1.y+s2.y+s3.y + bias.y;
            float gg = s0.z+s1.z+s2.z+s3.z + bias.z;
            float go = s0.w+s1.w+s2.w+s3.w + bias.w;
            c_state = fmaf(sigf(gf), c_state, sigf(gi) * tanh_acc(gg));
            float h = sigf(go) * tanh_acc(c_state);
            sq[bt*256 + d] = h;   // q(t+1)
        }
        __syncthreads();

        if (is_attn) {
            // ======== attention: direct-L2 stream, sector-minimal loads ========
            float4 qr[2][4];
            #pragma unroll
            for (int bt = 0; bt < 2; bt++)
                #pragma unroll
                for (int i = 0; i < 4; i++)
                    qr[bt][i] = *(const float4*)(sq + bt*256 + 32*i + 4*j);

            float rp[2][16];
            float lac[2] = {0.0f, 0.0f};
            #pragma unroll
            for (int bt = 0; bt < 2; bt++)
                #pragma unroll
                for (int k = 0; k < 16; k++) rp[bt][k] = 0.0f;

            // base pointer: row (wrp*4 + rp8), float4 offset j within 128B chunk 0
            const float4* pa0 = xa  + (size_t)(wrp * 4 + rp8) * 32 + j;
            const float4* pb0 = xbp + (size_t)(wrp * 4 + rp8) * 32 + j;

            #pragma unroll 2
            for (int it = 0; it < 32; it++) {
                uint64_t pol = (it < RES_IT) ? pol_last : pol_first;
                const float4* pa = pa0 + (size_t)it * 1024;   // 32 rows * 32 f4
                const float4* pb = pb0 + (size_t)it * 1024;

                float4 xra[4], xrb[4];
                #pragma unroll
                for (int i = 0; i < 4; i++) xra[i] = ldg_pol(pa + i * 8, pol);
                #pragma unroll
                for (int i = 0; i < 4; i++) xrb[i] = ldg_pol(pb + i * 8, pol);

                // batch a
                {
                    float e = 0.0f;
                    #pragma unroll
                    for (int i = 0; i < 4; i++) {
                        e = fmaf(xra[i].x, qr[0][i].x, e);
                        e = fmaf(xra[i].y, qr[0][i].y, e);
                        e = fmaf(xra[i].z, qr[0][i].z, e);
                        e = fmaf(xra[i].w, qr[0][i].w, e);
                    }
                    e += __shfl_xor_sync(0xffffffffu, e, 1);
                    e += __shfl_xor_sync(0xffffffffu, e, 2);
                    e += __shfl_xor_sync(0xffffffffu, e, 4);
                    float pw = __expf(e - 40.0f);   // |e| << 40 by construction
                    lac[0] += pw;
                    #pragma unroll
                    for (int i = 0; i < 4; i++) {
                        rp[0][4*i+0] = fmaf(pw, xra[i].x, rp[0][4*i+0]);
                        rp[0][4*i+1] = fmaf(pw, xra[i].y, rp[0][4*i+1]);
                        rp[0][4*i+2] = fmaf(pw, xra[i].z, rp[0][4*i+2]);
                        rp[0][4*i+3] = fmaf(pw, xra[i].w, rp[0][4*i+3]);
                    }
                }
                // batch b
                {
                    float e = 0.0f;
                    #pragma unroll
                    for (int i = 0; i < 4; i++) {
                        e = fmaf(xrb[i].x, qr[1][i].x, e);
                        e = fmaf(xrb[i].y, qr[1][i].y, e);
                        e = fmaf(xrb[i].z, qr[1][i].z, e);
                        e = fmaf(xrb[i].w, qr[1][i].w, e);
                    }
                    e += __shfl_xor_sync(0xffffffffu, e, 1);
                    e += __shfl_xor_sync(0xffffffffu, e, 2);
                    e += __shfl_xor_sync(0xffffffffu, e, 4);
                    float pw = __expf(e - 40.0f);
                    lac[1] += pw;
                    #pragma unroll
                    for (int i = 0; i < 4; i++) {
                        rp[1][4*i+0] = fmaf(pw, xrb[i].x, rp[1][4*i+0]);
                        rp[1][4*i+1] = fmaf(pw, xrb[i].y, rp[1][4*i+1]);
                        rp[1][4*i+2] = fmaf(pw, xrb[i].z, rp[1][4*i+2]);
                        rp[1][4*i+3] = fmaf(pw, xrb[i].w, rp[1][4*i+3]);
                    }
                }
            }

            // per-warp L reduce (j-lanes hold identical pw; xor 8,16 collapses
            // the 4 rowpart groups, each row counted once)
            #pragma unroll
            for (int bt = 0; bt < 2; bt++) {
                float lv = lac[bt];
                lv += __shfl_xor_sync(0xffffffffu, lv, 8);
                lv += __shfl_xor_sync(0xffffffffu, lv, 16);
                if (lane == 0) lred[bt * 8 + wrp] = lv;
                float* rw = red + (size_t)(bt * 256 + tid) * RSTR;
                #pragma unroll
                for (int i = 0; i < 4; i++)
                    *(float4*)(rw + 4 * i) = make_float4(rp[bt][4*i+0], rp[bt][4*i+1],
                                                         rp[bt][4*i+2], rp[bt][4*i+3]);
            }
        } else {
            // ======== gate warps: folded q-GEMV for NEXT step ========
            const float* qa = sq +       64 * (p2 & 1);
            const float* qb = sq + 256 + 64 * (p2 & 1);
            #pragma unroll 8
            for (int c = 0; c < 64; c++) {
                float va = qa[c], vb = qb[c];
                float4 w = Wqp[c * Dc];
                qacc_a.x=fmaf(va,w.x,qacc_a.x); qacc_a.y=fmaf(va,w.y,qacc_a.y);
                qacc_a.z=fmaf(va,w.z,qacc_a.z); qacc_a.w=fmaf(va,w.w,qacc_a.w);
                qacc_b.x=fmaf(vb,w.x,qacc_b.x); qacc_b.y=fmaf(vb,w.y,qacc_b.y);
                qacc_b.z=fmaf(vb,w.z,qacc_b.z); qacc_b.w=fmaf(vb,w.w,qacc_b.w);
            }
        }
        __syncthreads();

        // ---- phase 1: rsum halves across ALL 512 threads (16 iters each) ----
        // thread (q0', j) covers dims {32i+4j+k}; for dim d: j=(d>>2)&7,
        // entry kk = 4*(d>>5) + (d&3); sum over the 32 q0' threads (split 2x16)
        {
            int pair = tid & 255, half = tid >> 8;
            int bt = pair >> 7, dd = pair & 127;
            int jj = (dd >> 2) & 7;
            int kk = ((dd >> 5) << 2) | (dd & 3);
            const float* base = red + (size_t)(bt * 256 + half * 128 + jj) * RSTR + kk;
            float sacc = 0.0f;
            #pragma unroll
            for (int qq = 0; qq < 16; qq++)
                sacc += base[qq * 8 * RSTR];
            part[tid] = sacc;
        }
        __syncthreads();

        // ---- phase 2: combine + normalize (threads 0..255) ----
        if (tid < 256) {
            int bt = tid >> 7;
            float rsum = part[tid] + part[tid + 256];
            float Lx = ((lred[bt*8+0] + lred[bt*8+1]) + (lred[bt*8+2] + lred[bt*8+3]))
                     + ((lred[bt*8+4] + lred[bt*8+5]) + (lred[bt*8+6] + lred[bt*8+7]));
            sq[bt*256 + 128 + d] = __fdividef(rsum, Lx);
        }
        __syncthreads();
    }

    // ---- epilogue: out = q_star @ W_lin^T + b_lin ----
    {
        int bt = tid >> 8;
        int o  = tid & 255;
        float acc = b_lin[o];
        #pragma unroll 8
        for (int c = 0; c < QSc; c++)
            acc = fmaf(sq[bt*256 + c], g_WlinT[c * HIDc + o], acc);
        out[(size_t)(blockIdx.x * 2 + bt) * HIDc + o] = acc;
    }
}

extern "C" void kernel_launch(void* const* d_in, const int* in_sizes, int n_in,
                              void* d_out, int out_size) {
    const float* x     = (const float*)d_in[0];
    const float* W_ih  = (const float*)d_in[1];
    const float* W_hh  = (const float*)d_in[2];
    const float* b_ih  = (const float*)d_in[3];
    const float* b_hh  = (const float*)d_in[4];
    const float* W_lin = (const float*)d_in[5];
    const float* b_lin = (const float*)d_in[6];
    float* out = (float*)d_out;

    cudaFuncSetAttribute(s2s_kernel, cudaFuncAttributeMaxDynamicSharedMemorySize,
                         SMEM_TOTAL);
    prep_kernel<<<256, 256>>>(W_ih, W_hh, b_ih, b_hh, W_lin);
    s2s_kernel<<<Bc / 2, NTHR, SMEM_TOTAL>>>(x, b_lin, out);
}

// round 14
// speedup vs baseline: 1.5418x; 1.3183x over previous
#include <cuda_runtime.h>
#include <cstdint>

#define Bc   256
#define Nc   1024
#define Dc   128
#define QSc  256
#define HIDc 256
#define NTHR 512
#define TROWS 64
#define NTILES 16
#define TILE_B (TROWS * Dc * 4)   // 32768 B
#define PAIR_B (2 * TILE_B)       // one slot = both batches' tiles
#define NPAIRS 3
#define RES_TILES 10              // 128 CTA * 2 * 10 * 32KB = 80 MB pinned (< ~94MB pool)
#define RSTR 20                   // red row stride (floats): STS.128-aligned

// Folded weights (q_star[:128] == h lets W_ih[:, :128] + W_hh fold):
__device__ float4 g_Wq4[Dc * Dc];
__device__ float4 g_Wr4[Dc * Dc];
__device__ float4 g_bias4[Dc];
__device__ float  g_WlinT[QSc * HIDc];

// ---- dynamic SMEM (bytes) ----
// xs: 3 slot-pairs (ring). red/part overlay the IDLE pair (t%3) during reduction.
#define OFF_XS   0
#define SZ_XS    (NPAIRS * PAIR_B)            // 196608
#define OFF_GP   (OFF_XS + SZ_XS)             // float4[2][4][128] gate partials
#define SZ_GP    16384
#define OFF_LRED (OFF_GP + SZ_GP)             // float[2][8]
#define SZ_LRED  64
#define OFF_SQ   (OFF_LRED + SZ_LRED)         // float[2][256] = [q|r]
#define SZ_SQ    (2 * 256 * 4)
#define SMEM_TOTAL (OFF_SQ + SZ_SQ)           // 215104 B ≈ 210 KB

__global__ void prep_kernel(const float* __restrict__ W_ih,
                            const float* __restrict__ W_hh,
                            const float* __restrict__ b_ih,
                            const float* __restrict__ b_hh,
                            const float* __restrict__ W_lin) {
    int tid = blockIdx.x * blockDim.x + threadIdx.x;
    int nt  = gridDim.x * blockDim.x;
    for (int idx = tid; idx < Dc * Dc; idx += nt) {
        int c = idx >> 7, d = idx & 127;
        float4 w;
        w.x = W_ih[(d      ) * QSc + c] + W_hh[(d      ) * Dc + c];
        w.y = W_ih[(d + 128) * QSc + c] + W_hh[(d + 128) * Dc + c];
        w.z = W_ih[(d + 256) * QSc + c] + W_hh[(d + 256) * Dc + c];
        w.w = W_ih[(d + 384) * QSc + c] + W_hh[(d + 384) * Dc + c];
        g_Wq4[idx] = w;
        float4 v;
        v.x = W_ih[(d      ) * QSc + 128 + c];
        v.y = W_ih[(d + 128) * QSc + 128 + c];
        v.z = W_ih[(d + 256) * QSc + 128 + c];
        v.w = W_ih[(d + 384) * QSc + 128 + c];
        g_Wr4[idx] = v;
    }
    for (int d = tid; d < Dc; d += nt) {
        float4 bb;
        bb.x = b_ih[d      ] + b_hh[d      ];
        bb.y = b_ih[d + 128] + b_hh[d + 128];
        bb.z = b_ih[d + 256] + b_hh[d + 256];
        bb.w = b_ih[d + 384] + b_hh[d + 384];
        g_bias4[d] = bb;
    }
    for (int idx = tid; idx < QSc * HIDc; idx += nt) {
        int c = idx >> 8, o = idx & 255;
        g_WlinT[idx] = W_lin[o * QSc + c];
    }
}

__device__ __forceinline__ float sigf(float x) {
    return __fdividef(1.0f, 1.0f + __expf(-x));
}
__device__ __forceinline__ float tanh_acc(float x) {
    return __fdividef(2.0f, 1.0f + __expf(-2.0f * x)) - 1.0f;
}
__device__ __forceinline__ void cp16p(void* dst, const void* src, uint64_t pol) {
    uint32_t d = (uint32_t)__cvta_generic_to_shared(dst);
    asm volatile("cp.async.cg.shared.global.L2::cache_hint [%0], [%1], 16, %2;"
                 :: "r"(d), "l"(src), "l"(pol));
}
#define CP_COMMIT() asm volatile("cp.async.commit_group;")
#define CP_WAIT1()  asm volatile("cp.async.wait_group 1;")
#define CP_WAIT0()  asm volatile("cp.async.wait_group 0;")
#define BAR_ATTN()  asm volatile("bar.sync 1, 256;" ::: "memory")

__global__ void __launch_bounds__(NTHR, 1)
s2s_kernel(const float* __restrict__ x,
           const float* __restrict__ b_lin,
           float* __restrict__ out) {
    extern __shared__ char smem[];
    char*   xs   = smem + OFF_XS;
    float4* gp   = (float4*)(smem + OFF_GP);
    float*  lred = (float*)(smem + OFF_LRED);
    float*  sq   = (float*)(smem + OFF_SQ);   // per batch: [q(128) | r(128)]

    const int tid  = threadIdx.x;
    const int d    = tid & 127;
    const int p    = tid >> 7;
    const int lane = tid & 31;
    const int wrp  = tid >> 5;                // attn warps: 0..7
    const bool is_attn = (tid < 256);

    uint64_t pol_last, pol_first;
    asm("createpolicy.fractional.L2::evict_last.b64 %0, 1.0;"  : "=l"(pol_last));
    asm("createpolicy.fractional.L2::evict_first.b64 %0, 1.0;" : "=l"(pol_first));

    if (tid < 512) sq[tid] = 0.0f;
    float c_state = 0.0f;

    const float* xa  = x + (size_t)(blockIdx.x * 2    ) * Nc * Dc;
    const float* xbp = x + (size_t)(blockIdx.x * 2 + 1) * Nc * Dc;

    // attention-warp offsets (tid < 256)
    const int q0 = (tid & 255) >> 3;
    const int j  = tid & 7;
    int roff[4];
    #pragma unroll
    for (int i = 0; i < 4; i++) {
        int gi = 4 * j + i;
        int V  = ((q0 & 1) << 2) | (gi >> 3);
        roff[i] = q0 * 512 + ((gi >> 3) << 7) + (((gi & 7) ^ V) << 4);
    }
    int soff[8], doff[8];
    #pragma unroll
    for (int k = 0; k < 8; k++) {
        int G = (tid & 255) + 256 * k;
        int rr = G >> 5, g = G & 31;
        int V = ((rr & 1) << 2) | (g >> 3);
        soff[k] = rr * Dc + g * 4;
        doff[k] = rr * 512 + ((g >> 3) << 7) + (((g & 7) ^ V) << 4);
    }

    const int p2 = (tid >> 7) - 2;
    const float4* Wqp = g_Wq4 + (size_t)(64 * (p2 & 1)) * Dc + d;
    const float4* Wrp = g_Wr4 + (size_t)(32 * p) * Dc + d;
    const float4  bias = g_bias4[d];
    float4 qacc_a = make_float4(0.f,0.f,0.f,0.f);
    float4 qacc_b = make_float4(0.f,0.f,0.f,0.f);

    int ss = 0;   // slot of tile 0 this step == t % 3 (advances by 16 ≡ 1 mod 3)

    __syncthreads();

    for (int t = 0; t < Nc; t++) {
        // red/part overlay the pair that is IDLE this step (slot ss):
        // in-flight prefetches target slots (ss+1)%3 and (ss+2)%3 only.
        float* redp  = (float*)(xs + (size_t)ss * PAIR_B);
        float* partp = redp + 2 * 256 * RSTR;   // +40960 B (fits in 64 KB pair)

        // ---- prologue prefetch ONLY at t=0 (tiles 0,1 -> slots 0,1) ----
        if (is_attn && t == 0) {
            #pragma unroll
            for (int tt = 0; tt < 2; tt++) {
                const float* sa = xa  + (size_t)tt * TROWS * Dc;
                const float* sb = xbp + (size_t)tt * TROWS * Dc;
                char* da = xs + (size_t)tt * PAIR_B;
                char* db = da + TILE_B;
                #pragma unroll
                for (int k = 0; k < 8; k++) cp16p(da + doff[k], sa + soff[k], pol_last);
                #pragma unroll
                for (int k = 0; k < 8; k++) cp16p(db + doff[k], sb + soff[k], pol_last);
                CP_COMMIT();
            }
        }

        // ---- serial r-GEMV: 32 r-cols/thread; gate warps fold carried qacc ----
        {
            float4 aa, ab;
            if (is_attn) {
                aa = make_float4(0.f,0.f,0.f,0.f);
                ab = make_float4(0.f,0.f,0.f,0.f);
            } else {
                aa = qacc_a; ab = qacc_b;
                qacc_a = make_float4(0.f,0.f,0.f,0.f);
                qacc_b = make_float4(0.f,0.f,0.f,0.f);
            }
            const float* ra = sq +       128 + 32 * p;
            const float* rb = sq + 256 + 128 + 32 * p;
            #pragma unroll 8
            for (int cr = 0; cr < 32; cr++) {
                float va = ra[cr], vb = rb[cr];
                float4 w = Wrp[cr * Dc];
                aa.x=fmaf(va,w.x,aa.x); aa.y=fmaf(va,w.y,aa.y); aa.z=fmaf(va,w.z,aa.z); aa.w=fmaf(va,w.w,aa.w);
                ab.x=fmaf(vb,w.x,ab.x); ab.y=fmaf(vb,w.y,ab.y); ab.z=fmaf(vb,w.z,ab.z); ab.w=fmaf(vb,w.w,ab.w);
            }
            gp[(0 * 4 + p) * Dc + d] = aa;
            gp[(1 * 4 + p) * Dc + d] = ab;
        }
        __syncthreads();

        // ---- LSTM cell (threads 0..255) ----
        if (tid < 256) {
            int bt = tid >> 7;
            float4 s0 = gp[(bt*4+0)*Dc + d];
            float4 s1 = gp[(bt*4+1)*Dc + d];
            float4 s2 = gp[(bt*4+2)*Dc + d];
            float4 s3 = gp[(bt*4+3)*Dc + d];
            float gi = s0.x+s1.x+s2.x+s3.x + bias.x;
            float gf = s0.y+s1.y+s2.y+s3.y + bias.y;
            float gg = s0.z+s1.z+s2.z+s3.z + bias.z;
            float go = s0.w+s1.w+s2.w+s3.w + bias.w;
            c_state = fmaf(sigf(gf), c_state, sigf(gi) * tanh_acc(gg));
            float h = sigf(go) * tanh_acc(c_state);
            sq[bt*256 + d] = h;   // q(t+1)
        }
        __syncthreads();

        if (is_attn) {
            // ======== attention over 16 tiles, 3-slot ring, 1 barrier/tile ====
            float4 qr[2][4];
            #pragma unroll
            for (int bt = 0; bt < 2; bt++)
                #pragma unroll
                for (int i = 0; i < 4; i++)
                    qr[bt][i] = *(const float4*)(sq + bt*256 + 16*j + 4*i);

            float rp[2][16];
            float lac[2] = {0.0f, 0.0f};
            #pragma unroll
            for (int bt = 0; bt < 2; bt++)
                #pragma unroll
                for (int k = 0; k < 16; k++) rp[bt][k] = 0.0f;

            int s = ss;
            for (int tt = 0; tt < NTILES; tt++) {
                CP_WAIT1();        // my group for tile tt retired
                BAR_ATTN();        // all groups for tile tt visible; all threads
                                   // done reading tile tt-1 (frees slot (s+2)%3)

                // prefetch tile (tt+2)&15 into slot (s+2)%3 (read 2 iters ago)
                {
                    int nt = (tt + 2) & (NTILES - 1);
                    int ps = (s == 0) ? 2 : s - 1;   // (s+2)%3
                    uint64_t pol = (nt < RES_TILES) ? pol_last : pol_first;
                    const float* sa = xa  + (size_t)nt * TROWS * Dc;
                    const float* sb = xbp + (size_t)nt * TROWS * Dc;
                    char* da = xs + (size_t)ps * PAIR_B;
                    char* db = da + TILE_B;
                    #pragma unroll
                    for (int k = 0; k < 8; k++) cp16p(da + doff[k], sa + soff[k], pol);
                    #pragma unroll
                    for (int k = 0; k < 8; k++) cp16p(db + doff[k], sb + soff[k], pol);
                    CP_COMMIT();
                }

                // compute on slot s
                #pragma unroll
                for (int bt = 0; bt < 2; bt++) {
                    const char* tb = xs + (size_t)s * PAIR_B + bt * TILE_B;
                    #pragma unroll
                    for (int sub = 0; sub < 2; sub++) {
                        const char* rb2 = tb + sub * (32 * 512);
                        float4 xr[4];
                        float e = 0.0f;
                        #pragma unroll
                        for (int i = 0; i < 4; i++) {
                            xr[i] = *(const float4*)(rb2 + roff[i]);
                            e = fmaf(xr[i].x, qr[bt][i].x, e);
                            e = fmaf(xr[i].y, qr[bt][i].y, e);
                            e = fmaf(xr[i].z, qr[bt][i].z, e);
                            e = fmaf(xr[i].w, qr[bt][i].w, e);
                        }
                        e += __shfl_xor_sync(0xffffffffu, e, 1);
                        e += __shfl_xor_sync(0xffffffffu, e, 2);
                        e += __shfl_xor_sync(0xffffffffu, e, 4);
                        float pw = __expf(e - 40.0f);   // |e| << 40 by construction
                        lac[bt] += pw;
                        #pragma unroll
                        for (int i = 0; i < 4; i++) {
                            rp[bt][4*i+0] = fmaf(pw, xr[i].x, rp[bt][4*i+0]);
                            rp[bt][4*i+1] = fmaf(pw, xr[i].y, rp[bt][4*i+1]);
                            rp[bt][4*i+2] = fmaf(pw, xr[i].z, rp[bt][4*i+2]);
                            rp[bt][4*i+3] = fmaf(pw, xr[i].w, rp[bt][4*i+3]);
                        }
                    }
                }
                s = (s + 1 == NPAIRS) ? 0 : s + 1;
            }
            BAR_ATTN();   // tile 15 (slot ss) fully read before red overlays it

            // per-warp L reduce (lanes in a j-group hold identical pw)
            #pragma unroll
            for (int bt = 0; bt < 2; bt++) {
                float lv = lac[bt];
                lv += __shfl_xor_sync(0xffffffffu, lv, 8);
                lv += __shfl_xor_sync(0xffffffffu, lv, 16);
                if (lane == 0) lred[bt * 8 + wrp] = lv;
                float* rw = redp + (size_t)(bt * 256 + tid) * RSTR;
                #pragma unroll
                for (int i = 0; i < 4; i++)
                    *(float4*)(rw + 4 * i) = make_float4(rp[bt][4*i+0], rp[bt][4*i+1],
                                                         rp[bt][4*i+2], rp[bt][4*i+3]);
            }
        } else {
            // ======== gate warps: folded q-GEMV for NEXT step ========
            const float* qa = sq +       64 * (p2 & 1);
            const float* qb = sq + 256 + 64 * (p2 & 1);
            #pragma unroll 8
            for (int c = 0; c < 64; c++) {
                float va = qa[c], vb = qb[c];
                float4 w = Wqp[c * Dc];
                qacc_a.x=fmaf(va,w.x,qacc_a.x); qacc_a.y=fmaf(va,w.y,qacc_a.y);
                qacc_a.z=fmaf(va,w.z,qacc_a.z); qacc_a.w=fmaf(va,w.w,qacc_a.w);
                qacc_b.x=fmaf(vb,w.x,qacc_b.x); qacc_b.y=fmaf(vb,w.y,qacc_b.y);
                qacc_b.z=fmaf(vb,w.z,qacc_b.z); qacc_b.w=fmaf(vb,w.w,qacc_b.w);
            }
        }
        __syncthreads();

        // ---- phase 1: rsum halves across ALL 512 threads (16 iters each) ----
        {
            int pair = tid & 255, half = tid >> 8;
            int bt = pair >> 7, dd = pair & 127;
            int jj = dd >> 4, kk = dd & 15;
            const float* base = redp + (size_t)(bt * 256 + half * 128 + jj) * RSTR + kk;
            float sacc = 0.0f;
            #pragma unroll
            for (int qq = 0; qq < 16; qq++)
                sacc += base[qq * 8 * RSTR];
            partp[tid] = sacc;
        }
        __syncthreads();

        // ---- phase 2: combine + normalize (threads 0..255) ----
        if (tid < 256) {
            int bt = tid >> 7;
            float rsum = partp[tid] + partp[tid + 256];
            float Lx = ((lred[bt*8+0] + lred[bt*8+1]) + (lred[bt*8+2] + lred[bt*8+3]))
                     + ((lred[bt*8+4] + lred[bt*8+5]) + (lred[bt*8+6] + lred[bt*8+7]));
            sq[bt*256 + 128 + d] = __fdividef(rsum, Lx);
        }
        __syncthreads();

        ss = (ss + 1 == NPAIRS) ? 0 : ss + 1;   // 16 tiles ≡ 1 (mod 3)
    }

    if (is_attn) { CP_WAIT0(); }

    // ---- epilogue: out = q_star @ W_lin^T + b_lin ----
    {
        int bt = tid >> 8;
        int o  = tid & 255;
        float acc = b_lin[o];
        #pragma unroll 8
        for (int c = 0; c < QSc; c++)
            acc = fmaf(sq[bt*256 + c], g_WlinT[c * HIDc + o], acc);
        out[(size_t)(blockIdx.x * 2 + bt) * HIDc + o] = acc;
    }
}

extern "C" void kernel_launch(void* const* d_in, const int* in_sizes, int n_in,
                              void* d_out, int out_size) {
    const float* x     = (const float*)d_in[0];
    const float* W_ih  = (const float*)d_in[1];
    const float* W_hh  = (const float*)d_in[2];
    const float* b_ih  = (const float*)d_in[3];
    const float* b_hh  = (const float*)d_in[4];
    const float* W_lin = (const float*)d_in[5];
    const float* b_lin = (const float*)d_in[6];
    float* out = (float*)d_out;

    cudaFuncSetAttribute(s2s_kernel, cudaFuncAttributeMaxDynamicSharedMemorySize,
                         SMEM_TOTAL);
    prep_kernel<<<256, 256>>>(W_ih, W_hh, b_ih, b_hh, W_lin);
    s2s_kernel<<<Bc / 2, NTHR, SMEM_TOTAL>>>(x, b_lin, out);
}

// round 15
// speedup vs baseline: 1.6738x; 1.0856x over previous
#include <cuda_runtime.h>
#include <cstdint>

#define Bc   256
#define Nc   1024
#define Dc   128
#define QSc  256
#define HIDc 256
#define NTHR 512
#define TROWS 64
#define NTILES 16
#define TILE_B (TROWS * Dc * 4)   // 32768 B
#define PAIR_B (2 * TILE_B)       // one slot = both batches' tiles
#define NPAIRS 3
#define RES_TILES 9               // 72 MB pinned — measured optimum (10 => 80MB thrashes)
#define RSTR 20                   // red row stride (floats): STS.128-aligned

// Folded weights (q_star[:128] == h lets W_ih[:, :128] + W_hh fold):
__device__ float4 g_Wq4[Dc * Dc];
__device__ float4 g_Wr4[Dc * Dc];
__device__ float4 g_bias4[Dc];
__device__ float  g_WlinT[QSc * HIDc];

// ---- dynamic SMEM (bytes) ----
// xs: 3 slot-pairs (ring). red/part overlay the IDLE pair (t%3) during reduction.
#define OFF_XS   0
#define SZ_XS    (NPAIRS * PAIR_B)            // 196608
#define OFF_GP   (OFF_XS + SZ_XS)             // float4[2][4][128] gate partials
#define SZ_GP    16384
#define OFF_LRED (OFF_GP + SZ_GP)             // float[2][8]
#define SZ_LRED  64
#define OFF_SQ   (OFF_LRED + SZ_LRED)         // float[2][256] = [q|r]
#define SZ_SQ    (2 * 256 * 4)
#define SMEM_TOTAL (OFF_SQ + SZ_SQ)           // 215104 B ≈ 210 KB

__global__ void prep_kernel(const float* __restrict__ W_ih,
                            const float* __restrict__ W_hh,
                            const float* __restrict__ b_ih,
                            const float* __restrict__ b_hh,
                            const float* __restrict__ W_lin) {
    int tid = blockIdx.x * blockDim.x + threadIdx.x;
    int nt  = gridDim.x * blockDim.x;
    for (int idx = tid; idx < Dc * Dc; idx += nt) {
        int c = idx >> 7, d = idx & 127;
        float4 w;
        w.x = W_ih[(d      ) * QSc + c] + W_hh[(d      ) * Dc + c];
        w.y = W_ih[(d + 128) * QSc + c] + W_hh[(d + 128) * Dc + c];
        w.z = W_ih[(d + 256) * QSc + c] + W_hh[(d + 256) * Dc + c];
        w.w = W_ih[(d + 384) * QSc + c] + W_hh[(d + 384) * Dc + c];
        g_Wq4[idx] = w;
        float4 v;
        v.x = W_ih[(d      ) * QSc + 128 + c];
        v.y = W_ih[(d + 128) * QSc + 128 + c];
        v.z = W_ih[(d + 256) * QSc + 128 + c];
        v.w = W_ih[(d + 384) * QSc + 128 + c];
        g_Wr4[idx] = v;
    }
    for (int d = tid; d < Dc; d += nt) {
        float4 bb;
        bb.x = b_ih[d      ] + b_hh[d      ];
        bb.y = b_ih[d + 128] + b_hh[d + 128];
        bb.z = b_ih[d + 256] + b_hh[d + 256];
        bb.w = b_ih[d + 384] + b_hh[d + 384];
        g_bias4[d] = bb;
    }
    for (int idx = tid; idx < QSc * HIDc; idx += nt) {
        int c = idx >> 8, o = idx & 255;
        g_WlinT[idx] = W_lin[o * QSc + c];
    }
}

__device__ __forceinline__ float sigf(float x) {
    return __fdividef(1.0f, 1.0f + __expf(-x));
}
__device__ __forceinline__ float tanh_acc(float x) {
    return __fdividef(2.0f, 1.0f + __expf(-2.0f * x)) - 1.0f;
}
__device__ __forceinline__ void cp16p(void* dst, const void* src, uint64_t pol) {
    uint32_t d = (uint32_t)__cvta_generic_to_shared(dst);
    asm volatile("cp.async.cg.shared.global.L2::cache_hint [%0], [%1], 16, %2;"
                 :: "r"(d), "l"(src), "l"(pol));
}
#define CP_COMMIT() asm volatile("cp.async.commit_group;")
#define CP_WAIT1()  asm volatile("cp.async.wait_group 1;")
#define CP_WAIT0()  asm volatile("cp.async.wait_group 0;")
#define BAR_ATTN()  asm volatile("bar.sync 1, 256;" ::: "memory")

__global__ void __launch_bounds__(NTHR, 1)
s2s_kernel(const float* __restrict__ x,
           const float* __restrict__ b_lin,
           float* __restrict__ out) {
    extern __shared__ char smem[];
    char*   xs   = smem + OFF_XS;
    float4* gp   = (float4*)(smem + OFF_GP);
    float*  lred = (float*)(smem + OFF_LRED);
    float*  sq   = (float*)(smem + OFF_SQ);   // per batch: [q(128) | r(128)]

    const int tid  = threadIdx.x;
    const int d    = tid & 127;
    const int p    = tid >> 7;
    const int lane = tid & 31;
    const int wrp  = tid >> 5;                // attn warps: 0..7
    const bool is_attn = (tid < 256);

    uint64_t pol_last, pol_first;
    asm("createpolicy.fractional.L2::evict_last.b64 %0, 1.0;"  : "=l"(pol_last));
    asm("createpolicy.fractional.L2::evict_first.b64 %0, 1.0;" : "=l"(pol_first));

    if (tid < 512) sq[tid] = 0.0f;
    float c_state = 0.0f;

    const float* xa  = x + (size_t)(blockIdx.x * 2    ) * Nc * Dc;
    const float* xbp = x + (size_t)(blockIdx.x * 2 + 1) * Nc * Dc;

    // attention-warp offsets (tid < 256)
    const int q0 = (tid & 255) >> 3;
    const int j  = tid & 7;
    int roff[4];
    #pragma unroll
    for (int i = 0; i < 4; i++) {
        int gi = 4 * j + i;
        int V  = ((q0 & 1) << 2) | (gi >> 3);
        roff[i] = q0 * 512 + ((gi >> 3) << 7) + (((gi & 7) ^ V) << 4);
    }
    int soff[8], doff[8];
    #pragma unroll
    for (int k = 0; k < 8; k++) {
        int G = (tid & 255) + 256 * k;
        int rr = G >> 5, g = G & 31;
        int V = ((rr & 1) << 2) | (g >> 3);
        soff[k] = rr * Dc + g * 4;
        doff[k] = rr * 512 + ((g >> 3) << 7) + (((g & 7) ^ V) << 4);
    }

    const int p2 = (tid >> 7) - 2;
    const float4* Wqp = g_Wq4 + (size_t)(64 * (p2 & 1)) * Dc + d;
    const float4* Wrp = g_Wr4 + (size_t)(32 * p) * Dc + d;
    const float4  bias = g_bias4[d];
    float4 qacc_a = make_float4(0.f,0.f,0.f,0.f);
    float4 qacc_b = make_float4(0.f,0.f,0.f,0.f);

    int ss = 0;   // slot of tile 0 this step == t % 3 (advances by 16 ≡ 1 mod 3)

    __syncthreads();

    for (int t = 0; t < Nc; t++) {
        // red/part overlay the pair that is IDLE this step (slot ss):
        // in-flight prefetches target slots (ss+1)%3 and (ss+2)%3 only.
        float* redp  = (float*)(xs + (size_t)ss * PAIR_B);
        float* partp = redp + 2 * 256 * RSTR;   // +40960 B (fits in 64 KB pair)

        // ---- prologue prefetch ONLY at t=0 (tiles 0,1 -> slots 0,1) ----
        if (is_attn && t == 0) {
            #pragma unroll
            for (int tt = 0; tt < 2; tt++) {
                const float* sa = xa  + (size_t)tt * TROWS * Dc;
                const float* sb = xbp + (size_t)tt * TROWS * Dc;
                char* da = xs + (size_t)tt * PAIR_B;
                char* db = da + TILE_B;
                #pragma unroll
                for (int k = 0; k < 8; k++) cp16p(da + doff[k], sa + soff[k], pol_last);
                #pragma unroll
                for (int k = 0; k < 8; k++) cp16p(db + doff[k], sb + soff[k], pol_last);
                CP_COMMIT();
            }
        }

        // ---- serial r-GEMV: 32 r-cols/thread (deep unroll: max LDG batching
        //      on the step's critical path); gate warps fold carried qacc ----
        {
            float4 aa, ab;
            if (is_attn) {
                aa = make_float4(0.f,0.f,0.f,0.f);
                ab = make_float4(0.f,0.f,0.f,0.f);
            } else {
                aa = qacc_a; ab = qacc_b;
                qacc_a = make_float4(0.f,0.f,0.f,0.f);
                qacc_b = make_float4(0.f,0.f,0.f,0.f);
            }
            const float* ra = sq +       128 + 32 * p;
            const float* rb = sq + 256 + 128 + 32 * p;
            #pragma unroll 16
            for (int cr = 0; cr < 32; cr++) {
                float va = ra[cr], vb = rb[cr];
                float4 w = Wrp[cr * Dc];
                aa.x=fmaf(va,w.x,aa.x); aa.y=fmaf(va,w.y,aa.y); aa.z=fmaf(va,w.z,aa.z); aa.w=fmaf(va,w.w,aa.w);
                ab.x=fmaf(vb,w.x,ab.x); ab.y=fmaf(vb,w.y,ab.y); ab.z=fmaf(vb,w.z,ab.z); ab.w=fmaf(vb,w.w,ab.w);
            }
            gp[(0 * 4 + p) * Dc + d] = aa;
            gp[(1 * 4 + p) * Dc + d] = ab;
        }
        __syncthreads();

        // ---- LSTM cell (threads 0..255) ----
        if (tid < 256) {
            int bt = tid >> 7;
            float4 s0 = gp[(bt*4+0)*Dc + d];
            float4 s1 = gp[(bt*4+1)*Dc + d];
            float4 s2 = gp[(bt*4+2)*Dc + d];
            float4 s3 = gp[(bt*4+3)*Dc + d];
            float gi = s0.x+s1.x+s2.x+s3.x + bias.x;
            float gf = s0.y+s1.y+s2.y+s3.y + bias.y;
            float gg = s0.z+s1.z+s2.z+s3.z + bias.z;
            float go = s0.w+s1.w+s2.w+s3.w + bias.w;
            c_state = fmaf(sigf(gf), c_state, sigf(gi) * tanh_acc(gg));
            float h = sigf(go) * tanh_acc(c_state);
            sq[bt*256 + d] = h;   // q(t+1)
        }
        __syncthreads();

        if (is_attn) {
            // ======== attention over 16 tiles, 3-slot ring, 1 barrier/tile ====
            float4 qr[2][4];
            #pragma unroll
            for (int bt = 0; bt < 2; bt++)
                #pragma unroll
                for (int i = 0; i < 4; i++)
                    qr[bt][i] = *(const float4*)(sq + bt*256 + 16*j + 4*i);

            float rp[2][16];
            float lac[2] = {0.0f, 0.0f};
            #pragma unroll
            for (int bt = 0; bt < 2; bt++)
                #pragma unroll
                for (int k = 0; k < 16; k++) rp[bt][k] = 0.0f;

            int s = ss;
            for (int tt = 0; tt < NTILES; tt++) {
                CP_WAIT1();        // my group for tile tt retired
                BAR_ATTN();        // all groups for tile tt visible; all threads
                                   // done reading tile tt-1 (frees slot (s+2)%3)

                // prefetch tile (tt+2)&15 into slot (s+2)%3 (read 2 iters ago)
                {
                    int nt = (tt + 2) & (NTILES - 1);
                    int ps = (s == 0) ? 2 : s - 1;   // (s+2)%3
                    uint64_t pol = (nt < RES_TILES) ? pol_last : pol_first;
                    const float* sa = xa  + (size_t)nt * TROWS * Dc;
                    const float* sb = xbp + (size_t)nt * TROWS * Dc;
                    char* da = xs + (size_t)ps * PAIR_B;
                    char* db = da + TILE_B;
                    #pragma unroll
                    for (int k = 0; k < 8; k++) cp16p(da + doff[k], sa + soff[k], pol);
                    #pragma unroll
                    for (int k = 0; k < 8; k++) cp16p(db + doff[k], sb + soff[k], pol);
                    CP_COMMIT();
                }

                // compute on slot s
                #pragma unroll
                for (int bt = 0; bt < 2; bt++) {
                    const char* tb = xs + (size_t)s * PAIR_B + bt * TILE_B;
                    #pragma unroll
                    for (int sub = 0; sub < 2; sub++) {
                        const char* rb2 = tb + sub * (32 * 512);
                        float4 xr[4];
                        float e = 0.0f;
                        #pragma unroll
                        for (int i = 0; i < 4; i++) {
                            xr[i] = *(const float4*)(rb2 + roff[i]);
                            e = fmaf(xr[i].x, qr[bt][i].x, e);
                            e = fmaf(xr[i].y, qr[bt][i].y, e);
                            e = fmaf(xr[i].z, qr[bt][i].z, e);
                            e = fmaf(xr[i].w, qr[bt][i].w, e);
                        }
                        e += __shfl_xor_sync(0xffffffffu, e, 1);
                        e += __shfl_xor_sync(0xffffffffu, e, 2);
                        e += __shfl_xor_sync(0xffffffffu, e, 4);
                        float pw = __expf(e - 40.0f);   // |e| << 40 by construction
                        lac[bt] += pw;
                        #pragma unroll
                        for (int i = 0; i < 4; i++) {
                            rp[bt][4*i+0] = fmaf(pw, xr[i].x, rp[bt][4*i+0]);
                            rp[bt][4*i+1] = fmaf(pw, xr[i].y, rp[bt][4*i+1]);
                            rp[bt][4*i+2] = fmaf(pw, xr[i].z, rp[bt][4*i+2]);
                            rp[bt][4*i+3] = fmaf(pw, xr[i].w, rp[bt][4*i+3]);
                        }
                    }
                }
                s = (s + 1 == NPAIRS) ? 0 : s + 1;
            }
            BAR_ATTN();   // tile 15 (slot ss) fully read before red overlays it

            // per-warp L reduce (lanes in a j-group hold identical pw)
            #pragma unroll
            for (int bt = 0; bt < 2; bt++) {
                float lv = lac[bt];
                lv += __shfl_xor_sync(0xffffffffu, lv, 8);
                lv += __shfl_xor_sync(0xffffffffu, lv, 16);
                if (lane == 0) lred[bt * 8 + wrp] = lv;
                float* rw = redp + (size_t)(bt * 256 + tid) * RSTR;
                #pragma unroll
                for (int i = 0; i < 4; i++)
                    *(float4*)(rw + 4 * i) = make_float4(rp[bt][4*i+0], rp[bt][4*i+1],
                                                         rp[bt][4*i+2], rp[bt][4*i+3]);
            }
        } else {
            // ======== gate warps: folded q-GEMV for NEXT step ========
            const float* qa = sq +       64 * (p2 & 1);
            const float* qb = sq + 256 + 64 * (p2 & 1);
            #pragma unroll 8
            for (int c = 0; c < 64; c++) {
                float va = qa[c], vb = qb[c];
                float4 w = Wqp[c * Dc];
                qacc_a.x=fmaf(va,w.x,qacc_a.x); qacc_a.y=fmaf(va,w.y,qacc_a.y);
                qacc_a.z=fmaf(va,w.z,qacc_a.z); qacc_a.w=fmaf(va,w.w,qacc_a.w);
                qacc_b.x=fmaf(vb,w.x,qacc_b.x); qacc_b.y=fmaf(vb,w.y,qacc_b.y);
                qacc_b.z=fmaf(vb,w.z,qacc_b.z); qacc_b.w=fmaf(vb,w.w,qacc_b.w);
            }
        }
        __syncthreads();

        // ---- phase 1: rsum halves across ALL 512 threads (16 iters each) ----
        {
            int pair = tid & 255, half = tid >> 8;
            int bt = pair >> 7, dd = pair & 127;
            int jj = dd >> 4, kk = dd & 15;
            const float* base = redp + (size_t)(bt * 256 + half * 128 + jj) * RSTR + kk;
            float sacc = 0.0f;
            #pragma unroll
            for (int qq = 0; qq < 16; qq++)
                sacc += base[qq * 8 * RSTR];
            partp[tid] = sacc;
        }
        __syncthreads();

        // ---- phase 2: combine + normalize (threads 0..255) ----
        if (tid < 256) {
            int bt = tid >> 7;
            float rsum = partp[tid] + partp[tid + 256];
            float Lx = ((lred[bt*8+0] + lred[bt*8+1]) + (lred[bt*8+2] + lred[bt*8+3]))
                     + ((lred[bt*8+4] + lred[bt*8+5]) + (lred[bt*8+6] + lred[bt*8+7]));
            sq[bt*256 + 128 + d] = __fdividef(rsum, Lx);
        }
        __syncthreads();

        ss = (ss + 1 == NPAIRS) ? 0 : ss + 1;   // 16 tiles ≡ 1 (mod 3)
    }

    if (is_attn) { CP_WAIT0(); }

    // ---- epilogue: out = q_star @ W_lin^T + b_lin ----
    {
        int bt = tid >> 8;
        int o  = tid & 255;
        float acc = b_lin[o];
        #pragma unroll 8
        for (int c = 0; c < QSc; c++)
            acc = fmaf(sq[bt*256 + c], g_WlinT[c * HIDc + o], acc);
        out[(size_t)(blockIdx.x * 2 + bt) * HIDc + o] = acc;
    }
}

extern "C" void kernel_launch(void* const* d_in, const int* in_sizes, int n_in,
                              void* d_out, int out_size) {
    const float* x     = (const float*)d_in[0];
    const float* W_ih  = (const float*)d_in[1];
    const float* W_hh  = (const float*)d_in[2];
    const float* b_ih  = (const float*)d_in[3];
    const float* b_hh  = (const float*)d_in[4];
    const float* W_lin = (const float*)d_in[5];
    const float* b_lin = (const float*)d_in[6];
    float* out = (float*)d_out;

    cudaFuncSetAttribute(s2s_kernel, cudaFuncAttributeMaxDynamicSharedMemorySize,
                         SMEM_TOTAL);
    prep_kernel<<<256, 256>>>(W_ih, W_hh, b_ih, b_hh, W_lin);
    s2s_kernel<<<Bc / 2, NTHR, SMEM_TOTAL>>>(x, b_lin, out);
}

// round 16
// speedup vs baseline: 1.6873x; 1.0081x over previous
#include <cuda_runtime.h>
#include <cstdint>

#define Bc   256
#define Nc   1024
#define Dc   128
#define QSc  256
#define HIDc 256
#define NTHR 512
#define TROWS 64
#define NTILES 16
#define TILE_B (TROWS * Dc * 4)   // 32768 B
#define PAIR_B (2 * TILE_B)       // one slot = both batches' tiles
#define NPAIRS 3
#define RES_TILES 9               // 72 MB pinned — measured optimum (80/96MB thrash)
#define RSTR 20                   // red row stride (floats): STS.128-aligned

// Folded weights (q_star[:128] == h lets W_ih[:, :128] + W_hh fold):
__device__ float4 g_Wq4[Dc * Dc];
__device__ float4 g_Wr4[Dc * Dc];
__device__ float4 g_bias4[Dc];
__device__ float  g_WlinT[QSc * HIDc];

// ---- dynamic SMEM (bytes) ----
// xs: 3 slot-pairs (ring). red/part overlay the IDLE pair (t%3) during reduction.
#define OFF_XS   0
#define SZ_XS    (NPAIRS * PAIR_B)            // 196608
#define OFF_GP   (OFF_XS + SZ_XS)             // float4[2][4][128] gate partials
#define SZ_GP    16384
#define OFF_LRED (OFF_GP + SZ_GP)             // float[2][8]
#define SZ_LRED  64
#define OFF_SQ   (OFF_LRED + SZ_LRED)         // float[2][256] = [q|r]
#define SZ_SQ    (2 * 256 * 4)
#define SMEM_TOTAL (OFF_SQ + SZ_SQ)           // 215104 B ≈ 210 KB

__global__ void prep_kernel(const float* __restrict__ W_ih,
                            const float* __restrict__ W_hh,
                            const float* __restrict__ b_ih,
                            const float* __restrict__ b_hh,
                            const float* __restrict__ W_lin) {
    int tid = blockIdx.x * blockDim.x + threadIdx.x;
    int nt  = gridDim.x * blockDim.x;
    for (int idx = tid; idx < Dc * Dc; idx += nt) {
        int c = idx >> 7, d = idx & 127;
        float4 w;
        w.x = W_ih[(d      ) * QSc + c] + W_hh[(d      ) * Dc + c];
        w.y = W_ih[(d + 128) * QSc + c] + W_hh[(d + 128) * Dc + c];
        w.z = W_ih[(d + 256) * QSc + c] + W_hh[(d + 256) * Dc + c];
        w.w = W_ih[(d + 384) * QSc + c] + W_hh[(d + 384) * Dc + c];
        g_Wq4[idx] = w;
        float4 v;
        v.x = W_ih[(d      ) * QSc + 128 + c];
        v.y = W_ih[(d + 128) * QSc + 128 + c];
        v.z = W_ih[(d + 256) * QSc + 128 + c];
        v.w = W_ih[(d + 384) * QSc + 128 + c];
        g_Wr4[idx] = v;
    }
    for (int d = tid; d < Dc; d += nt) {
        float4 bb;
        bb.x = b_ih[d      ] + b_hh[d      ];
        bb.y = b_ih[d + 128] + b_hh[d + 128];
        bb.z = b_ih[d + 256] + b_hh[d + 256];
        bb.w = b_ih[d + 384] + b_hh[d + 384];
        g_bias4[d] = bb;
    }
    for (int idx = tid; idx < QSc * HIDc; idx += nt) {
        int c = idx >> 8, o = idx & 255;
        g_WlinT[idx] = W_lin[o * QSc + c];
    }
}

__device__ __forceinline__ float sigf(float x) {
    return __fdividef(1.0f, 1.0f + __expf(-x));
}
__device__ __forceinline__ float tanh_acc(float x) {
    return __fdividef(2.0f, 1.0f + __expf(-2.0f * x)) - 1.0f;
}
__device__ __forceinline__ void cp16p(void* dst, const void* src, uint64_t pol) {
    uint32_t d = (uint32_t)__cvta_generic_to_shared(dst);
    asm volatile("cp.async.cg.shared.global.L2::cache_hint [%0], [%1], 16, %2;"
                 :: "r"(d), "l"(src), "l"(pol));
}
#define CP_COMMIT() asm volatile("cp.async.commit_group;")
#define CP_WAIT1()  asm volatile("cp.async.wait_group 1;")
#define CP_WAIT0()  asm volatile("cp.async.wait_group 0;")
#define BAR_ATTN()  asm volatile("bar.sync 1, 256;" ::: "memory")

__global__ void __launch_bounds__(NTHR, 1)
s2s_kernel(const float* __restrict__ x,
           const float* __restrict__ b_lin,
           float* __restrict__ out) {
    extern __shared__ char smem[];
    char*   xs   = smem + OFF_XS;
    float4* gp   = (float4*)(smem + OFF_GP);
    float*  lred = (float*)(smem + OFF_LRED);
    float*  sq   = (float*)(smem + OFF_SQ);   // per batch: [q(128) | r(128)]

    const int tid  = threadIdx.x;
    const int d    = tid & 127;
    const int p    = tid >> 7;
    const int lane = tid & 31;
    const int wrp  = tid >> 5;                // attn warps: 0..7
    const bool is_attn = (tid < 256);

    uint64_t pol_last, pol_first;
    asm("createpolicy.fractional.L2::evict_last.b64 %0, 1.0;"  : "=l"(pol_last));
    asm("createpolicy.fractional.L2::evict_first.b64 %0, 1.0;" : "=l"(pol_first));

    if (tid < 512) sq[tid] = 0.0f;
    float c_state = 0.0f;

    const float* xa  = x + (size_t)(blockIdx.x * 2    ) * Nc * Dc;
    const float* xbp = x + (size_t)(blockIdx.x * 2 + 1) * Nc * Dc;

    // attention-warp offsets (tid < 256)
    const int q0 = (tid & 255) >> 3;
    const int j  = tid & 7;
    int roff[4];
    #pragma unroll
    for (int i = 0; i < 4; i++) {
        int gi = 4 * j + i;
        int V  = ((q0 & 1) << 2) | (gi >> 3);
        roff[i] = q0 * 512 + ((gi >> 3) << 7) + (((gi & 7) ^ V) << 4);
    }
    int soff[8], doff[8];
    #pragma unroll
    for (int k = 0; k < 8; k++) {
        int G = (tid & 255) + 256 * k;
        int rr = G >> 5, g = G & 31;
        int V = ((rr & 1) << 2) | (g >> 3);
        soff[k] = rr * Dc + g * 4;
        doff[k] = rr * 512 + ((g >> 3) << 7) + (((g & 7) ^ V) << 4);
    }

    const int p2 = (tid >> 7) - 2;
    const float4* Wqp = g_Wq4 + (size_t)(64 * (p2 & 1)) * Dc + d;
    const float4* Wrp = g_Wr4 + (size_t)(32 * p) * Dc + d;
    const float4  bias = g_bias4[d];
    float4 qacc_a = make_float4(0.f,0.f,0.f,0.f);
    float4 qacc_b = make_float4(0.f,0.f,0.f,0.f);

    int ss = 0;   // slot of tile 0 this step == t % 3 (advances by 16 ≡ 1 mod 3)

    __syncthreads();

    for (int t = 0; t < Nc; t++) {
        // red/part overlay the pair that is IDLE this step (slot ss):
        // in-flight prefetches target slots (ss+1)%3 and (ss+2)%3 only.
        float* redp  = (float*)(xs + (size_t)ss * PAIR_B);
        float* partp = redp + 2 * 256 * RSTR;   // +40960 B (fits in 64 KB pair)

        // ---- prologue prefetch ONLY at t=0 (tiles 0,1 -> slots 0,1) ----
        if (is_attn && t == 0) {
            #pragma unroll
            for (int tt = 0; tt < 2; tt++) {
                const float* sa = xa  + (size_t)tt * TROWS * Dc;
                const float* sb = xbp + (size_t)tt * TROWS * Dc;
                char* da = xs + (size_t)tt * PAIR_B;
                char* db = da + TILE_B;
                #pragma unroll
                for (int k = 0; k < 8; k++) cp16p(da + doff[k], sa + soff[k], pol_last);
                #pragma unroll
                for (int k = 0; k < 8; k++) cp16p(db + doff[k], sb + soff[k], pol_last);
                CP_COMMIT();
            }
        }

        // ---- serial r-GEMV: 32 r-cols/thread; gate warps fold carried qacc ----
        {
            float4 aa, ab;
            if (is_attn) {
                aa = make_float4(0.f,0.f,0.f,0.f);
                ab = make_float4(0.f,0.f,0.f,0.f);
            } else {
                aa = qacc_a; ab = qacc_b;
                qacc_a = make_float4(0.f,0.f,0.f,0.f);
                qacc_b = make_float4(0.f,0.f,0.f,0.f);
            }
            const float* ra = sq +       128 + 32 * p;
            const float* rb = sq + 256 + 128 + 32 * p;
            #pragma unroll 8
            for (int cr = 0; cr < 32; cr++) {
                float va = ra[cr], vb = rb[cr];
                float4 w = Wrp[cr * Dc];
                aa.x=fmaf(va,w.x,aa.x); aa.y=fmaf(va,w.y,aa.y); aa.z=fmaf(va,w.z,aa.z); aa.w=fmaf(va,w.w,aa.w);
                ab.x=fmaf(vb,w.x,ab.x); ab.y=fmaf(vb,w.y,ab.y); ab.z=fmaf(vb,w.z,ab.z); ab.w=fmaf(vb,w.w,ab.w);
            }
            gp[(0 * 4 + p) * Dc + d] = aa;
            gp[(1 * 4 + p) * Dc + d] = ab;
        }
        __syncthreads();

        // ---- LSTM cell (threads 0..255) ----
        if (tid < 256) {
            int bt = tid >> 7;
            float4 s0 = gp[(bt*4+0)*Dc + d];
            float4 s1 = gp[(bt*4+1)*Dc + d];
            float4 s2 = gp[(bt*4+2)*Dc + d];
            float4 s3 = gp[(bt*4+3)*Dc + d];
            float gi = s0.x+s1.x+s2.x+s3.x + bias.x;
            float gf = s0.y+s1.y+s2.y+s3.y + bias.y;
            float gg = s0.z+s1.z+s2.z+s3.z + bias.z;
            float go = s0.w+s1.w+s2.w+s3.w + bias.w;
            c_state = fmaf(sigf(gf), c_state, sigf(gi) * tanh_acc(gg));
            float h = sigf(go) * tanh_acc(c_state);
            sq[bt*256 + d] = h;   // q(t+1)
        }
        __syncthreads();

        if (is_attn) {
            // ======== attention over 16 tiles, 3-slot ring, 1 barrier/tile ====
            float4 qr[2][4];
            #pragma unroll
            for (int bt = 0; bt < 2; bt++)
                #pragma unroll
                for (int i = 0; i < 4; i++)
                    qr[bt][i] = *(const float4*)(sq + bt*256 + 16*j + 4*i);

            float rp[2][16];
            float lac[2] = {0.0f, 0.0f};
            #pragma unroll
            for (int bt = 0; bt < 2; bt++)
                #pragma unroll
                for (int k = 0; k < 16; k++) rp[bt][k] = 0.0f;

            int s = ss;
            for (int tt = 0; tt < NTILES; tt++) {
                CP_WAIT1();        // my group for tile tt retired
                BAR_ATTN();        // all groups for tile tt visible; all threads
                                   // done reading tile tt-1 (frees slot (s+2)%3)

                // prefetch tile (tt+2)&15 into slot (s+2)%3 (read 2 iters ago)
                {
                    int nt = (tt + 2) & (NTILES - 1);
                    int ps = (s == 0) ? 2 : s - 1;   // (s+2)%3
                    uint64_t pol = (nt < RES_TILES) ? pol_last : pol_first;
                    const float* sa = xa  + (size_t)nt * TROWS * Dc;
                    const float* sb = xbp + (size_t)nt * TROWS * Dc;
                    char* da = xs + (size_t)ps * PAIR_B;
                    char* db = da + TILE_B;
                    #pragma unroll
                    for (int k = 0; k < 8; k++) cp16p(da + doff[k], sa + soff[k], pol);
                    #pragma unroll
                    for (int k = 0; k < 8; k++) cp16p(db + doff[k], sb + soff[k], pol);
                    CP_COMMIT();
                }

                // compute on slot s
                #pragma unroll
                for (int bt = 0; bt < 2; bt++) {
                    const char* tb = xs + (size_t)s * PAIR_B + bt * TILE_B;
                    #pragma unroll
                    for (int sub = 0; sub < 2; sub++) {
                        const char* rb2 = tb + sub * (32 * 512);
                        float4 xr[4];
                        float e = 0.0f;
                        #pragma unroll
                        for (int i = 0; i < 4; i++) {
                            xr[i] = *(const float4*)(rb2 + roff[i]);
                            e = fmaf(xr[i].x, qr[bt][i].x, e);
                            e = fmaf(xr[i].y, qr[bt][i].y, e);
                            e = fmaf(xr[i].z, qr[bt][i].z, e);
                            e = fmaf(xr[i].w, qr[bt][i].w, e);
                        }
                        e += __shfl_xor_sync(0xffffffffu, e, 1);
                        e += __shfl_xor_sync(0xffffffffu, e, 2);
                        e += __shfl_xor_sync(0xffffffffu, e, 4);
                        float pw = __expf(e - 40.0f);   // |e| << 40 by construction
                        lac[bt] += pw;
                        #pragma unroll
                        for (int i = 0; i < 4; i++) {
                            rp[bt][4*i+0] = fmaf(pw, xr[i].x, rp[bt][4*i+0]);
                            rp[bt][4*i+1] = fmaf(pw, xr[i].y, rp[bt][4*i+1]);
                            rp[bt][4*i+2] = fmaf(pw, xr[i].z, rp[bt][4*i+2]);
                            rp[bt][4*i+3] = fmaf(pw, xr[i].w, rp[bt][4*i+3]);
                        }
                    }
                }
                s = (s + 1 == NPAIRS) ? 0 : s + 1;
            }
            BAR_ATTN();   // tile 15 (slot ss) fully read before red overlays it

            // per-warp L reduce (lanes in a j-group hold identical pw)
            #pragma unroll
            for (int bt = 0; bt < 2; bt++) {
                float lv = lac[bt];
                lv += __shfl_xor_sync(0xffffffffu, lv, 8);
                lv += __shfl_xor_sync(0xffffffffu, lv, 16);
                if (lane == 0) lred[bt * 8 + wrp] = lv;
                float* rw = redp + (size_t)(bt * 256 + tid) * RSTR;
                #pragma unroll
                for (int i = 0; i < 4; i++)
                    *(float4*)(rw + 4 * i) = make_float4(rp[bt][4*i+0], rp[bt][4*i+1],
                                                         rp[bt][4*i+2], rp[bt][4*i+3]);
            }
        } else {
            // ======== gate warps: folded q-GEMV for NEXT step ========
            const float* qa = sq +       64 * (p2 & 1);
            const float* qb = sq + 256 + 64 * (p2 & 1);
            #pragma unroll 8
            for (int c = 0; c < 64; c++) {
                float va = qa[c], vb = qb[c];
                float4 w = Wqp[c * Dc];
                qacc_a.x=fmaf(va,w.x,qacc_a.x); qacc_a.y=fmaf(va,w.y,qacc_a.y);
                qacc_a.z=fmaf(va,w.z,qacc_a.z); qacc_a.w=fmaf(va,w.w,qacc_a.w);
                qacc_b.x=fmaf(vb,w.x,qacc_b.x); qacc_b.y=fmaf(vb,w.y,qacc_b.y);
                qacc_b.z=fmaf(vb,w.z,qacc_b.z); qacc_b.w=fmaf(vb,w.w,qacc_b.w);
            }
        }
        __syncthreads();

        // ---- phase 1: rsum halves across ALL 512 threads (16 iters each) ----
        {
            int pair = tid & 255, half = tid >> 8;
            int bt = pair >> 7, dd = pair & 127;
            int jj = dd >> 4, kk = dd & 15;
            const float* base = redp + (size_t)(bt * 256 + half * 128 + jj) * RSTR + kk;
            float sacc = 0.0f;
            #pragma unroll
            for (int qq = 0; qq < 16; qq++)
                sacc += base[qq * 8 * RSTR];
            partp[tid] = sacc;
        }
        __syncthreads();

        // ---- phase 2: combine + normalize (threads 0..255) ----
        if (tid < 256) {
            int bt = tid >> 7;
            float rsum = partp[tid] + partp[tid + 256];
            float Lx = ((lred[bt*8+0] + lred[bt*8+1]) + (lred[bt*8+2] + lred[bt*8+3]))
                     + ((lred[bt*8+4] + lred[bt*8+5]) + (lred[bt*8+6] + lred[bt*8+7]));
            sq[bt*256 + 128 + d] = __fdividef(rsum, Lx);
        }
        __syncthreads();

        ss = (ss + 1 == NPAIRS) ? 0 : ss + 1;   // 16 tiles ≡ 1 (mod 3)
    }

    if (is_attn) { CP_WAIT0(); }

    // ---- epilogue: out = q_star @ W_lin^T + b_lin ----
    {
        int bt = tid >> 8;
        int o  = tid & 255;
        float acc = b_lin[o];
        #pragma unroll 8
        for (int c = 0; c < QSc; c++)
            acc = fmaf(sq[bt*256 + c], g_WlinT[c * HIDc + o], acc);
        out[(size_t)(blockIdx.x * 2 + bt) * HIDc + o] = acc;
    }
}

extern "C" void kernel_launch(void* const* d_in, const int* in_sizes, int n_in,
                              void* d_out, int out_size) {
    const float* x     = (const float*)d_in[0];
    const float* W_ih  = (const float*)d_in[1];
    const float* W_hh  = (const float*)d_in[2];
    const float* b_ih  = (const float*)d_in[3];
    const float* b_hh  = (const float*)d_in[4];
    const float* W_lin = (const float*)d_in[5];
    const float* b_lin = (const float*)d_in[6];
    float* out = (float*)d_out;

    cudaFuncSetAttribute(s2s_kernel, cudaFuncAttributeMaxDynamicSharedMemorySize,
                         SMEM_TOTAL);
    prep_kernel<<<256, 256>>>(W_ih, W_hh, b_ih, b_hh, W_lin);
    s2s_kernel<<<Bc / 2, NTHR, SMEM_TOTAL>>>(x, b_lin, out);
}

// round 17
// speedup vs baseline: 1.6918x; 1.0027x over previous
#include <cuda_runtime.h>
#include <cstdint>

#define Bc   256
#define Nc   1024
#define Dc   128
#define QSc  256
#define HIDc 256
#define NTHR 512
#define TROWS 64
#define NTILES 16
#define TILE_B (TROWS * Dc * 4)   // 32768 B
#define PAIR_B (2 * TILE_B)       // one slot = both batches' tiles
#define NPAIRS 3
#define RES_TILES 9               // 72 MB pinned — measured optimum (80/96MB thrash)
#define RSTR 20                   // red row stride (floats): STS.128-aligned

// Folded weights (q_star[:128] == h lets W_ih[:, :128] + W_hh fold):
__device__ float4 g_Wq4[Dc * Dc];
__device__ float4 g_Wr4[Dc * Dc];
__device__ float4 g_bias4[Dc];
__device__ float  g_WlinT[QSc * HIDc];

// ---- dynamic SMEM (bytes) ----
// xs: 3 slot-pairs (ring). red/part overlay the IDLE pair (t%3) during reduction.
#define OFF_XS   0
#define SZ_XS    (NPAIRS * PAIR_B)            // 196608
#define OFF_GP   (OFF_XS + SZ_XS)             // float4[2][4][128] gate partials
#define SZ_GP    16384
#define OFF_LRED (OFF_GP + SZ_GP)             // float[2][8]
#define SZ_LRED  64
#define OFF_SQ   (OFF_LRED + SZ_LRED)         // float[2][256] = [q|r]
#define SZ_SQ    (2 * 256 * 4)
#define SMEM_TOTAL (OFF_SQ + SZ_SQ)           // 215104 B ≈ 210 KB

__global__ void prep_kernel(const float* __restrict__ W_ih,
                            const float* __restrict__ W_hh,
                            const float* __restrict__ b_ih,
                            const float* __restrict__ b_hh,
                            const float* __restrict__ W_lin) {
    int tid = blockIdx.x * blockDim.x + threadIdx.x;
    int nt  = gridDim.x * blockDim.x;
    for (int idx = tid; idx < Dc * Dc; idx += nt) {
        int c = idx >> 7, d = idx & 127;
        float4 w;
        w.x = W_ih[(d      ) * QSc + c] + W_hh[(d      ) * Dc + c];
        w.y = W_ih[(d + 128) * QSc + c] + W_hh[(d + 128) * Dc + c];
        w.z = W_ih[(d + 256) * QSc + c] + W_hh[(d + 256) * Dc + c];
        w.w = W_ih[(d + 384) * QSc + c] + W_hh[(d + 384) * Dc + c];
        g_Wq4[idx] = w;
        float4 v;
        v.x = W_ih[(d      ) * QSc + 128 + c];
        v.y = W_ih[(d + 128) * QSc + 128 + c];
        v.z = W_ih[(d + 256) * QSc + 128 + c];
        v.w = W_ih[(d + 384) * QSc + 128 + c];
        g_Wr4[idx] = v;
    }
    for (int d = tid; d < Dc; d += nt) {
        float4 bb;
        bb.x = b_ih[d      ] + b_hh[d      ];
        bb.y = b_ih[d + 128] + b_hh[d + 128];
        bb.z = b_ih[d + 256] + b_hh[d + 256];
        bb.w = b_ih[d + 384] + b_hh[d + 384];
        g_bias4[d] = bb;
    }
    for (int idx = tid; idx < QSc * HIDc; idx += nt) {
        int c = idx >> 8, o = idx & 255;
        g_WlinT[idx] = W_lin[o * QSc + c];
    }
}

__device__ __forceinline__ float sigf(float x) {
    return __fdividef(1.0f, 1.0f + __expf(-x));
}
__device__ __forceinline__ float tanh_acc(float x) {
    return __fdividef(2.0f, 1.0f + __expf(-2.0f * x)) - 1.0f;
}
__device__ __forceinline__ void cp16p(void* dst, const void* src, uint64_t pol) {
    uint32_t d = (uint32_t)__cvta_generic_to_shared(dst);
    asm volatile("cp.async.cg.shared.global.L2::cache_hint [%0], [%1], 16, %2;"
                 :: "r"(d), "l"(src), "l"(pol));
}
#define CP_COMMIT() asm volatile("cp.async.commit_group;")
#define CP_WAIT1()  asm volatile("cp.async.wait_group 1;")
#define CP_WAIT0()  asm volatile("cp.async.wait_group 0;")
#define BAR_ATTN()  asm volatile("bar.sync 1, 256;" ::: "memory")

__global__ void __launch_bounds__(NTHR, 1)
s2s_kernel(const float* __restrict__ x,
           const float* __restrict__ b_lin,
           float* __restrict__ out) {
    extern __shared__ char smem[];
    char*   xs   = smem + OFF_XS;
    float4* gp   = (float4*)(smem + OFF_GP);
    float*  lred = (float*)(smem + OFF_LRED);
    float*  sq   = (float*)(smem + OFF_SQ);   // per batch: [q(128) | r(128)]

    const int tid  = threadIdx.x;
    const int d    = tid & 127;
    const int p    = tid >> 7;
    const int lane = tid & 31;
    const int wrp  = tid >> 5;                // attn warps: 0..7
    const bool is_attn = (tid < 256);

    uint64_t pol_last, pol_first;
    asm("createpolicy.fractional.L2::evict_last.b64 %0, 1.0;"  : "=l"(pol_last));
    asm("createpolicy.fractional.L2::evict_first.b64 %0, 1.0;" : "=l"(pol_first));

    if (tid < 512) sq[tid] = 0.0f;
    float c_state = 0.0f;

    const float* xa  = x + (size_t)(blockIdx.x * 2    ) * Nc * Dc;
    const float* xbp = x + (size_t)(blockIdx.x * 2 + 1) * Nc * Dc;

    // attention-warp offsets (tid < 256)
    const int q0 = (tid & 255) >> 3;
    const int j  = tid & 7;
    int roff[4];
    #pragma unroll
    for (int i = 0; i < 4; i++) {
        int gi = 4 * j + i;
        int V  = ((q0 & 1) << 2) | (gi >> 3);
        roff[i] = q0 * 512 + ((gi >> 3) << 7) + (((gi & 7) ^ V) << 4);
    }
    int soff[8], doff[8];
    #pragma unroll
    for (int k = 0; k < 8; k++) {
        int G = (tid & 255) + 256 * k;
        int rr = G >> 5, g = G & 31;
        int V = ((rr & 1) << 2) | (g >> 3);
        soff[k] = rr * Dc + g * 4;
        doff[k] = rr * 512 + ((g >> 3) << 7) + (((g & 7) ^ V) << 4);
    }

    const int p2 = (tid >> 7) - 2;
    const float4* Wqp = g_Wq4 + (size_t)(64 * (p2 & 1)) * Dc + d;
    const float4* Wrp = g_Wr4 + (size_t)(32 * p) * Dc + d;
    const float4  bias = g_bias4[d];
    float4 qacc_a = make_float4(0.f,0.f,0.f,0.f);
    float4 qacc_b = make_float4(0.f,0.f,0.f,0.f);

    int ss = 0;   // slot of tile 0 this step == t % 3 (advances by 16 ≡ 1 mod 3)

    __syncthreads();

    for (int t = 0; t < Nc; t++) {
        // red/part overlay the pair that is IDLE this step (slot ss):
        // in-flight prefetches target slots (ss+1)%3 and (ss+2)%3 only.
        float* redp  = (float*)(xs + (size_t)ss * PAIR_B);
        float* partp = redp + 2 * 256 * RSTR;   // +40960 B (fits in 64 KB pair)

        // ---- prologue prefetch ONLY at t=0 (tiles 0,1 -> slots 0,1) ----
        if (is_attn && t == 0) {
            #pragma unroll
            for (int tt = 0; tt < 2; tt++) {
                const float* sa = xa  + (size_t)tt * TROWS * Dc;
                const float* sb = xbp + (size_t)tt * TROWS * Dc;
                char* da = xs + (size_t)tt * PAIR_B;
                char* db = da + TILE_B;
                #pragma unroll
                for (int k = 0; k < 8; k++) cp16p(da + doff[k], sa + soff[k], pol_last);
                #pragma unroll
                for (int k = 0; k < 8; k++) cp16p(db + doff[k], sb + soff[k], pol_last);
                CP_COMMIT();
            }
        }

        // ---- serial r-GEMV: 32 r-cols/thread; gate warps fold carried qacc ----
        {
            float4 aa, ab;
            if (is_attn) {
                aa = make_float4(0.f,0.f,0.f,0.f);
                ab = make_float4(0.f,0.f,0.f,0.f);
            } else {
                aa = qacc_a; ab = qacc_b;
                qacc_a = make_float4(0.f,0.f,0.f,0.f);
                qacc_b = make_float4(0.f,0.f,0.f,0.f);
            }
            const float* ra = sq +       128 + 32 * p;
            const float* rb = sq + 256 + 128 + 32 * p;
            #pragma unroll 8
            for (int cr = 0; cr < 32; cr++) {
                float va = ra[cr], vb = rb[cr];
                float4 w = Wrp[cr * Dc];
                aa.x=fmaf(va,w.x,aa.x); aa.y=fmaf(va,w.y,aa.y); aa.z=fmaf(va,w.z,aa.z); aa.w=fmaf(va,w.w,aa.w);
                ab.x=fmaf(vb,w.x,ab.x); ab.y=fmaf(vb,w.y,ab.y); ab.z=fmaf(vb,w.z,ab.z); ab.w=fmaf(vb,w.w,ab.w);
            }
            gp[(0 * 4 + p) * Dc + d] = aa;
            gp[(1 * 4 + p) * Dc + d] = ab;
        }
        __syncthreads();

        // ---- LSTM cell (threads 0..255) ----
        if (tid < 256) {
            int bt = tid >> 7;
            float4 s0 = gp[(bt*4+0)*Dc + d];
            float4 s1 = gp[(bt*4+1)*Dc + d];
            float4 s2 = gp[(bt*4+2)*Dc + d];
            float4 s3 = gp[(bt*4+3)*Dc + d];
            float gi = s0.x+s1.x+s2.x+s3.x + bias.x;
            float gf = s0.y+s1.y+s2.y+s3.y + bias.y;
            float gg = s0.z+s1.z+s2.z+s3.z + bias.z;
            float go = s0.w+s1.w+s2.w+s3.w + bias.w;
            c_state = fmaf(sigf(gf), c_state, sigf(gi) * tanh_acc(gg));
            float h = sigf(go) * tanh_acc(c_state);
            sq[bt*256 + d] = h;   // q(t+1)
        }
        __syncthreads();

        if (is_attn) {
            // ======== attention over 16 tiles, 3-slot ring, 1 barrier/tile ====
            float4 qr[2][4];
            #pragma unroll
            for (int bt = 0; bt < 2; bt++)
                #pragma unroll
                for (int i = 0; i < 4; i++)
                    qr[bt][i] = *(const float4*)(sq + bt*256 + 16*j + 4*i);

            float rp[2][16];
            float lac[2] = {0.0f, 0.0f};
            #pragma unroll
            for (int bt = 0; bt < 2; bt++)
                #pragma unroll
                for (int k = 0; k < 16; k++) rp[bt][k] = 0.0f;

            int s = ss;
            for (int tt = 0; tt < NTILES; tt++) {
                CP_WAIT1();        // my group for tile tt retired
                BAR_ATTN();        // all groups for tile tt visible; all threads
                                   // done reading tile tt-1 (frees slot (s+2)%3)

                // prefetch tile (tt+2)&15 into slot (s+2)%3 (read 2 iters ago)
                {
                    int nt = (tt + 2) & (NTILES - 1);
                    int ps = (s == 0) ? 2 : s - 1;   // (s+2)%3
                    uint64_t pol = (nt < RES_TILES) ? pol_last : pol_first;
                    const float* sa = xa  + (size_t)nt * TROWS * Dc;
                    const float* sb = xbp + (size_t)nt * TROWS * Dc;
                    char* da = xs + (size_t)ps * PAIR_B;
                    char* db = da + TILE_B;
                    #pragma unroll
                    for (int k = 0; k < 8; k++) cp16p(da + doff[k], sa + soff[k], pol);
                    #pragma unroll
                    for (int k = 0; k < 8; k++) cp16p(db + doff[k], sb + soff[k], pol);
                    CP_COMMIT();
                }

                // compute on slot s
                #pragma unroll
                for (int bt = 0; bt < 2; bt++) {
                    const char* tb = xs + (size_t)s * PAIR_B + bt * TILE_B;
                    #pragma unroll
                    for (int sub = 0; sub < 2; sub++) {
                        const char* rb2 = tb + sub * (32 * 512);
                        float4 xr[4];
                        float e = 0.0f;
                        #pragma unroll
                        for (int i = 0; i < 4; i++) {
                            xr[i] = *(const float4*)(rb2 + roff[i]);
                            e = fmaf(xr[i].x, qr[bt][i].x, e);
                            e = fmaf(xr[i].y, qr[bt][i].y, e);
                            e = fmaf(xr[i].z, qr[bt][i].z, e);
                            e = fmaf(xr[i].w, qr[bt][i].w, e);
                        }
                        e += __shfl_xor_sync(0xffffffffu, e, 1);
                        e += __shfl_xor_sync(0xffffffffu, e, 2);
                        e += __shfl_xor_sync(0xffffffffu, e, 4);
                        float pw = __expf(e - 40.0f);   // |e| << 40 by construction
                        lac[bt] += pw;
                        #pragma unroll
                        for (int i = 0; i < 4; i++) {
                            rp[bt][4*i+0] = fmaf(pw, xr[i].x, rp[bt][4*i+0]);
                            rp[bt][4*i+1] = fmaf(pw, xr[i].y, rp[bt][4*i+1]);
                            rp[bt][4*i+2] = fmaf(pw, xr[i].z, rp[bt][4*i+2]);
                            rp[bt][4*i+3] = fmaf(pw, xr[i].w, rp[bt][4*i+3]);
                        }
                    }
                }
                s = (s + 1 == NPAIRS) ? 0 : s + 1;
            }
            BAR_ATTN();   // tile 15 (slot ss) fully read before red overlays it

            // per-warp L reduce (lanes in a j-group hold identical pw)
            #pragma unroll
            for (int bt = 0; bt < 2; bt++) {
                float lv = lac[bt];
                lv += __shfl_xor_sync(0xffffffffu, lv, 8);
                lv += __shfl_xor_sync(0xffffffffu, lv, 16);
                if (lane == 0) lred[bt * 8 + wrp] = lv;
                float* rw = redp + (size_t)(bt * 256 + tid) * RSTR;
                #pragma unroll
                for (int i = 0; i < 4; i++)
                    *(float4*)(rw + 4 * i) = make_float4(rp[bt][4*i+0], rp[bt][4*i+1],
                                                         rp[bt][4*i+2], rp[bt][4*i+3]);
            }
        } else {
            // ======== gate warps: folded q-GEMV for NEXT step ========
            const float* qa = sq +       64 * (p2 & 1);
            const float* qb = sq + 256 + 64 * (p2 & 1);
            #pragma unroll 8
            for (int c = 0; c < 64; c++) {
                float va = qa[c], vb = qb[c];
                float4 w = Wqp[c * Dc];
                qacc_a.x=fmaf(va,w.x,qacc_a.x); qacc_a.y=fmaf(va,w.y,qacc_a.y);
                qacc_a.z=fmaf(va,w.z,qacc_a.z); qacc_a.w=fmaf(va,w.w,qacc_a.w);
                qacc_b.x=fmaf(vb,w.x,qacc_b.x); qacc_b.y=fmaf(vb,w.y,qacc_b.y);
                qacc_b.z=fmaf(vb,w.z,qacc_b.z); qacc_b.w=fmaf(vb,w.w,qacc_b.w);
            }
        }
        __syncthreads();

        // ---- phase 1: rsum halves across ALL 512 threads (16 iters each) ----
        {
            int pair = tid & 255, half = tid >> 8;
            int bt = pair >> 7, dd = pair & 127;
            int jj = dd >> 4, kk = dd & 15;
            const float* base = redp + (size_t)(bt * 256 + half * 128 + jj) * RSTR + kk;
            float sacc = 0.0f;
            #pragma unroll
            for (int qq = 0; qq < 16; qq++)
                sacc += base[qq * 8 * RSTR];
            partp[tid] = sacc;
        }
        __syncthreads();

        // ---- phase 2: combine + normalize (threads 0..255) ----
        if (tid < 256) {
            int bt = tid >> 7;
            float rsum = partp[tid] + partp[tid + 256];
            float Lx = ((lred[bt*8+0] + lred[bt*8+1]) + (lred[bt*8+2] + lred[bt*8+3]))
                     + ((lred[bt*8+4] + lred[bt*8+5]) + (lred[bt*8+6] + lred[bt*8+7]));
            sq[bt*256 + 128 + d] = __fdividef(rsum, Lx);
        }
        __syncthreads();

        ss = (ss + 1 == NPAIRS) ? 0 : ss + 1;   // 16 tiles ≡ 1 (mod 3)
    }

    if (is_attn) { CP_WAIT0(); }

    // ---- epilogue: out = q_star @ W_lin^T + b_lin ----
    {
        int bt = tid >> 8;
        int o  = tid & 255;
        float acc = b_lin[o];
        #pragma unroll 8
        for (int c = 0; c < QSc; c++)
            acc = fmaf(sq[bt*256 + c], g_WlinT[c * HIDc + o], acc);
        out[(size_t)(blockIdx.x * 2 + bt) * HIDc + o] = acc;
    }
}

extern "C" void kernel_launch(void* const* d_in, const int* in_sizes, int n_in,
                              void* d_out, int out_size) {
    const float* x     = (const float*)d_in[0];
    const float* W_ih  = (const float*)d_in[1];
    const float* W_hh  = (const float*)d_in[2];
    const float* b_ih  = (const float*)d_in[3];
    const float* b_hh  = (const float*)d_in[4];
    const float* W_lin = (const float*)d_in[5];
    const float* b_lin = (const float*)d_in[6];
    float* out = (float*)d_out;

    cudaFuncSetAttribute(s2s_kernel, cudaFuncAttributeMaxDynamicSharedMemorySize,
                         SMEM_TOTAL);
    prep_kernel<<<256, 256>>>(W_ih, W_hh, b_ih, b_hh, W_lin);
    s2s_kernel<<<Bc / 2, NTHR, SMEM_TOTAL>>>(x, b_lin, out);
}